// round 1
// baseline (speedup 1.0000x reference)
#include <cuda_runtime.h>
#include <math.h>
#include <stdint.h>

// Problem constants
#define Lc 12
#define Hc 768
#define NHc 12
#define DHc 64
#define FFc 3072
#define Vc 21128
#define Sc 512
#define Bc 8
#define Mc (Bc*Sc)          // 4096 tokens
#define SEPc 102
#define LN_EPS 1e-12f

// ---------------- Device scratch (static; no runtime allocation) ----------------
__device__ float g_x[Mc*Hc];
__device__ float g_q[Mc*Hc];
__device__ float g_k[Mc*Hc];
__device__ float g_v[Mc*Hc];
__device__ float g_ctx[Mc*Hc];
__device__ float g_proj[Mc*Hc];
__device__ float g_ffn[(size_t)Mc*FFc];
__device__ float g_logits[(size_t)Mc*Vc];
__device__ float g_nll[Mc];
__device__ float g_valid[Mc];
__device__ int   g_sep[Bc];

// ---------------- [SEP] position per batch row ----------------
__global__ void sep_kernel(const int* __restrict__ ids) {
    int b = threadIdx.x;
    if (b < Bc) {
        int s = Sc - 1;
        for (int i = 0; i < Sc; i++) {
            if (ids[b*Sc + i] == SEPc) { s = i; break; }
        }
        g_sep[b] = s;
    }
}

// ---------------- Embedding + LayerNorm ----------------
__global__ void embed_ln_kernel(const int* __restrict__ ids,
                                const float* __restrict__ we,
                                const float* __restrict__ pe,
                                const float* __restrict__ te,
                                const float* __restrict__ gg,
                                const float* __restrict__ bb)
{
    int row = blockIdx.x;              // token index
    int s   = row % Sc;
    int tid = threadIdx.x;
    __shared__ float buf[Hc];
    __shared__ float red[256];
    int id = ids[row];
    float lsum = 0.f;
    for (int j = tid; j < Hc; j += 256) {
        float val = we[(size_t)id*Hc + j] + pe[s*Hc + j] + te[j];
        buf[j] = val;
        lsum += val;
    }
    red[tid] = lsum; __syncthreads();
    for (int o = 128; o > 0; o >>= 1) { if (tid < o) red[tid] += red[tid+o]; __syncthreads(); }
    float mean = red[0] * (1.0f/Hc);
    __syncthreads();
    float lsq = 0.f;
    for (int j = tid; j < Hc; j += 256) { float d = buf[j]-mean; lsq += d*d; }
    red[tid] = lsq; __syncthreads();
    for (int o = 128; o > 0; o >>= 1) { if (tid < o) red[tid] += red[tid+o]; __syncthreads(); }
    float inv = rsqrtf(red[0]*(1.0f/Hc) + LN_EPS);
    for (int j = tid; j < Hc; j += 256)
        g_x[(size_t)row*Hc + j] = (buf[j]-mean)*inv*gg[j] + bb[j];
}

// ---------------- Residual add + LayerNorm (x = LN(x + t)) ----------------
__global__ void add_ln_kernel(float* __restrict__ x, const float* __restrict__ t,
                              const float* __restrict__ gg, const float* __restrict__ bb)
{
    int row = blockIdx.x;
    int tid = threadIdx.x;
    __shared__ float buf[Hc];
    __shared__ float red[256];
    float lsum = 0.f;
    for (int j = tid; j < Hc; j += 256) {
        float val = x[(size_t)row*Hc + j] + t[(size_t)row*Hc + j];
        buf[j] = val;
        lsum += val;
    }
    red[tid] = lsum; __syncthreads();
    for (int o = 128; o > 0; o >>= 1) { if (tid < o) red[tid] += red[tid+o]; __syncthreads(); }
    float mean = red[0] * (1.0f/Hc);
    __syncthreads();
    float lsq = 0.f;
    for (int j = tid; j < Hc; j += 256) { float d = buf[j]-mean; lsq += d*d; }
    red[tid] = lsq; __syncthreads();
    for (int o = 128; o > 0; o >>= 1) { if (tid < o) red[tid] += red[tid+o]; __syncthreads(); }
    float inv = rsqrtf(red[0]*(1.0f/Hc) + LN_EPS);
    for (int j = tid; j < Hc; j += 256)
        x[(size_t)row*Hc + j] = (buf[j]-mean)*inv*gg[j] + bb[j];
}

// ---------------- Generic SGEMM: C = act(A[M,K] @ B[K,N] + bias) ----------------
// BM=BN=128, BK=8, 8x8 per thread, 256 threads. K % 8 == 0, M % 128 == 0, N % 4 == 0.
template<int ACT>
__global__ __launch_bounds__(256)
void gemm_bias_kernel(const float* __restrict__ A, const float* __restrict__ Bm,
                      const float* __restrict__ bias, float* __restrict__ C,
                      int M, int N, int K)
{
    __shared__ float As[8][128];
    __shared__ float Bs[8][128];
    const int tid  = threadIdx.x;
    const int trow = tid >> 4;          // 0..15
    const int tcol = tid & 15;          // 0..15
    const int byr  = blockIdx.y * 128;
    const int bxc  = blockIdx.x * 128;

    float acc[8][8];
#pragma unroll
    for (int i = 0; i < 8; i++)
#pragma unroll
        for (int j = 0; j < 8; j++) acc[i][j] = 0.f;

    const int aRow = tid >> 1;          // 0..127
    const int aCol = (tid & 1) * 4;     // 0 or 4
    const int bRow = tid >> 5;          // 0..7
    const int bCol = (tid & 31) * 4;    // 0..124
    const float* aBase = A + (size_t)(byr + aRow) * K + aCol;
    const int gc = bxc + bCol;

    for (int k0 = 0; k0 < K; k0 += 8) {
        float4 a4 = *reinterpret_cast<const float4*>(aBase + k0);
        As[aCol+0][aRow] = a4.x; As[aCol+1][aRow] = a4.y;
        As[aCol+2][aRow] = a4.z; As[aCol+3][aRow] = a4.w;
        float4 b4 = make_float4(0.f,0.f,0.f,0.f);
        if (gc < N)
            b4 = *reinterpret_cast<const float4*>(Bm + (size_t)(k0 + bRow) * N + gc);
        Bs[bRow][bCol+0] = b4.x; Bs[bRow][bCol+1] = b4.y;
        Bs[bRow][bCol+2] = b4.z; Bs[bRow][bCol+3] = b4.w;
        __syncthreads();
#pragma unroll
        for (int kk = 0; kk < 8; kk++) {
            float ar[8], br[8];
#pragma unroll
            for (int i = 0; i < 8; i++) ar[i] = As[kk][trow*8 + i];
#pragma unroll
            for (int j = 0; j < 8; j++) br[j] = Bs[kk][tcol*8 + j];
#pragma unroll
            for (int i = 0; i < 8; i++)
#pragma unroll
                for (int j = 0; j < 8; j++)
                    acc[i][j] = fmaf(ar[i], br[j], acc[i][j]);
        }
        __syncthreads();
    }

#pragma unroll
    for (int i = 0; i < 8; i++) {
        int row = byr + trow*8 + i;
#pragma unroll
        for (int j = 0; j < 8; j++) {
            int col = bxc + tcol*8 + j;
            if (col < N) {
                float val = acc[i][j] + bias[col];
                if (ACT == 1) val = 0.5f * val * (1.0f + erff(val * 0.70710678118654752f));
                C[(size_t)row * N + col] = val;
            }
        }
    }
}

// ---------------- Fused attention (scores + mask + softmax + ctx) ----------------
// One block (128 thr) per (b, h, q). K/V rows for a (b,h) are heavily L2-reused.
__global__ void attn_kernel(const float* __restrict__ q, const float* __restrict__ k,
                            const float* __restrict__ v, float* __restrict__ ctx)
{
    const int qi  = blockIdx.x;
    const int h   = blockIdx.y;
    const int b   = blockIdx.z;
    const int tid = threadIdx.x;
    __shared__ float sQ[DHc];
    __shared__ float sP[Sc];
    __shared__ float red[128];

    const size_t baseQ = ((size_t)(b*Sc + qi) * Hc) + h*DHc;
    if (tid < DHc) sQ[tid] = q[baseQ + tid];
    __syncthreads();

    const int sp = g_sep[b];
    float lmax = -3.4e38f;
    for (int kk = tid; kk < Sc; kk += 128) {
        const float* kr = k + ((size_t)(b*Sc + kk) * Hc) + h*DHc;
        float s = 0.f;
#pragma unroll
        for (int d = 0; d < DHc; d += 4) {
            float4 k4 = *reinterpret_cast<const float4*>(kr + d);
            s += sQ[d]*k4.x + sQ[d+1]*k4.y + sQ[d+2]*k4.z + sQ[d+3]*k4.w;
        }
        s *= 0.125f;                                   // 1/sqrt(64)
        bool allowed = (kk <= qi) || (qi <= sp && kk <= sp);
        if (!allowed) s -= 1e4f;                       // matches (1-mask)*-1e4 bias
        sP[kk] = s;
        lmax = fmaxf(lmax, s);
    }
    red[tid] = lmax; __syncthreads();
    for (int o = 64; o > 0; o >>= 1) { if (tid < o) red[tid] = fmaxf(red[tid], red[tid+o]); __syncthreads(); }
    const float m = red[0];
    __syncthreads();

    float lsum = 0.f;
    for (int kk = tid; kk < Sc; kk += 128) {
        float e = expf(sP[kk] - m);
        sP[kk] = e;
        lsum += e;
    }
    red[tid] = lsum; __syncthreads();
    for (int o = 64; o > 0; o >>= 1) { if (tid < o) red[tid] += red[tid+o]; __syncthreads(); }
    const float invsum = 1.0f / red[0];
    __syncthreads();

    const int d    = tid & 63;
    const int half = tid >> 6;
    float acc = 0.f;
    const float* vb = v + ((size_t)b*Sc*Hc) + h*DHc + d;
    for (int kk = half*256; kk < half*256 + 256; kk++)
        acc += sP[kk] * vb[(size_t)kk * Hc];
    red[tid] = acc; __syncthreads();
    if (tid < 64)
        ctx[baseQ + tid] = (red[tid] + red[tid+64]) * invsum;
}

// ---------------- Per-row log-softmax NLL ----------------
__global__ void row_loss_kernel(const int* __restrict__ labels)
{
    int row = blockIdx.x;
    int tid = threadIdx.x;
    const float* lr = g_logits + (size_t)row * Vc;
    __shared__ float red[256];

    float m = -3.4e38f;
    for (int j = tid; j < Vc; j += 256) m = fmaxf(m, lr[j]);
    red[tid] = m; __syncthreads();
    for (int o = 128; o > 0; o >>= 1) { if (tid < o) red[tid] = fmaxf(red[tid], red[tid+o]); __syncthreads(); }
    m = red[0];
    __syncthreads();

    float s = 0.f;
    for (int j = tid; j < Vc; j += 256) s += expf(lr[j] - m);
    red[tid] = s; __syncthreads();
    for (int o = 128; o > 0; o >>= 1) { if (tid < o) red[tid] += red[tid+o]; __syncthreads(); }

    if (tid == 0) {
        int lab = labels[row];
        if (lab >= 0) {
            g_nll[row]   = (m + logf(red[0])) - lr[lab];
            g_valid[row] = 1.0f;
        } else {
            g_nll[row]   = 0.0f;
            g_valid[row] = 0.0f;
        }
    }
}

// ---------------- Deterministic final reduction ----------------
__global__ void loss_reduce_kernel(float* __restrict__ out)
{
    __shared__ float rs[1024];
    __shared__ float rc[1024];
    int tid = threadIdx.x;
    float s = 0.f, c = 0.f;
    for (int i = tid; i < Mc; i += 1024) { s += g_nll[i]; c += g_valid[i]; }
    rs[tid] = s; rc[tid] = c; __syncthreads();
    for (int o = 512; o > 0; o >>= 1) {
        if (tid < o) { rs[tid] += rs[tid+o]; rc[tid] += rc[tid+o]; }
        __syncthreads();
    }
    if (tid == 0) out[0] = rs[0] / fmaxf(rc[0], 1.0f);
}

// ---------------- Host orchestration ----------------
static void run_gemm(const float* A, const float* W, const float* bias, float* C,
                     int M, int N, int K, bool gelu)
{
    dim3 grid((N + 127) / 128, M / 128);
    if (gelu) gemm_bias_kernel<1><<<grid, 256>>>(A, W, bias, C, M, N, K);
    else      gemm_bias_kernel<0><<<grid, 256>>>(A, W, bias, C, M, N, K);
}

extern "C" void kernel_launch(void* const* d_in, const int* in_sizes, int n_in,
                              void* d_out, int out_size)
{
    (void)in_sizes; (void)n_in; (void)out_size;

    const int*   ids      = (const int*)  d_in[0];
    const int*   labels   = (const int*)  d_in[1];
    const float* word_emb = (const float*)d_in[2];
    const float* pos_emb  = (const float*)d_in[3];
    const float* type_emb = (const float*)d_in[4];
    const float* eg       = (const float*)d_in[5];
    const float* eb       = (const float*)d_in[6];
    const float* Wq       = (const float*)d_in[7];
    const float* bq       = (const float*)d_in[8];
    const float* Wk       = (const float*)d_in[9];
    const float* bk       = (const float*)d_in[10];
    const float* Wv       = (const float*)d_in[11];
    const float* bv       = (const float*)d_in[12];
    const float* Wo       = (const float*)d_in[13];
    const float* bo       = (const float*)d_in[14];
    const float* l1g      = (const float*)d_in[15];
    const float* l1b      = (const float*)d_in[16];
    const float* Wi       = (const float*)d_in[17];
    const float* bi       = (const float*)d_in[18];
    const float* Wd       = (const float*)d_in[19];
    const float* bd       = (const float*)d_in[20];
    const float* l2g      = (const float*)d_in[21];
    const float* l2b      = (const float*)d_in[22];
    const float* Wc       = (const float*)d_in[23];
    const float* bc       = (const float*)d_in[24];

    void* p;
    cudaGetSymbolAddress(&p, g_x);     float* px    = (float*)p;
    cudaGetSymbolAddress(&p, g_q);     float* pq    = (float*)p;
    cudaGetSymbolAddress(&p, g_k);     float* pk    = (float*)p;
    cudaGetSymbolAddress(&p, g_v);     float* pv    = (float*)p;
    cudaGetSymbolAddress(&p, g_ctx);   float* pctx  = (float*)p;
    cudaGetSymbolAddress(&p, g_proj);  float* pproj = (float*)p;
    cudaGetSymbolAddress(&p, g_ffn);   float* pffn  = (float*)p;
    cudaGetSymbolAddress(&p, g_logits);float* plog  = (float*)p;

    sep_kernel<<<1, 32>>>(ids);
    embed_ln_kernel<<<Mc, 256>>>(ids, word_emb, pos_emb, type_emb, eg, eb);

    for (int l = 0; l < Lc; l++) {
        const size_t wHH = (size_t)l * Hc * Hc;
        run_gemm(px,   Wq + wHH, bq + (size_t)l*Hc, pq, Mc, Hc, Hc, false);
        run_gemm(px,   Wk + wHH, bk + (size_t)l*Hc, pk, Mc, Hc, Hc, false);
        run_gemm(px,   Wv + wHH, bv + (size_t)l*Hc, pv, Mc, Hc, Hc, false);
        attn_kernel<<<dim3(Sc, NHc, Bc), 128>>>(pq, pk, pv, pctx);
        run_gemm(pctx, Wo + wHH, bo + (size_t)l*Hc, pproj, Mc, Hc, Hc, false);
        add_ln_kernel<<<Mc, 256>>>(px, pproj, l1g + (size_t)l*Hc, l1b + (size_t)l*Hc);
        run_gemm(px,   Wi + (size_t)l*Hc*FFc, bi + (size_t)l*FFc, pffn, Mc, FFc, Hc, true);
        run_gemm(pffn, Wd + (size_t)l*FFc*Hc, bd + (size_t)l*Hc, pproj, Mc, Hc, FFc, false);
        add_ln_kernel<<<Mc, 256>>>(px, pproj, l2g + (size_t)l*Hc, l2b + (size_t)l*Hc);
    }

    run_gemm(px, Wc, bc, plog, Mc, Vc, Hc, false);
    row_loss_kernel<<<Mc, 256>>>(labels);
    loss_reduce_kernel<<<1, 1024>>>((float*)d_out);
}

// round 3
// speedup vs baseline: 4.2053x; 4.2053x over previous
#include <cuda_runtime.h>
#include <math.h>
#include <stdint.h>

// Problem constants
#define Lc 12
#define Hc 768
#define NHc 12
#define DHc 64
#define FFc 3072
#define Vc 21128
#define Sc 512
#define Bc 8
#define Mc (Bc*Sc)          // 4096 tokens
#define SEPc 102
#define LN_EPS 1e-12f

// ---------------- Device scratch (static; no runtime allocation) ----------------
__device__ float g_x[Mc*Hc];
__device__ float g_q[Mc*Hc];
__device__ float g_k[Mc*Hc];
__device__ float g_v[Mc*Hc];
__device__ float g_ctx[Mc*Hc];
__device__ float g_proj[Mc*Hc];
__device__ float g_ffn[(size_t)Mc*FFc];
__device__ float g_logits[(size_t)Mc*Vc];
__device__ float g_nll[Mc];
__device__ float g_valid[Mc];
__device__ int   g_sep[Bc];
// Transposed (N-major, K-contiguous) tf32-rounded weights
__device__ float g_WqT[Lc*Hc*Hc];
__device__ float g_WkT[Lc*Hc*Hc];
__device__ float g_WvT[Lc*Hc*Hc];
__device__ float g_WoT[Lc*Hc*Hc];
__device__ float g_WiT[(size_t)Lc*FFc*Hc];
__device__ float g_WdT[(size_t)Lc*Hc*FFc];
__device__ float g_WcT[(size_t)Vc*Hc];

// ---------------- small PTX helpers (compute_103-safe) ----------------
__device__ __forceinline__ uint32_t smem_to_u32(const void* smem_ptr) {
    uint32_t addr;
    asm("{ .reg .u64 tmp; cvta.to.shared.u64 tmp, %1; cvt.u32.u64 %0, tmp; }"
        : "=r"(addr) : "l"(smem_ptr));
    return addr;
}
__device__ __forceinline__ float tf32r(float x) {
    uint32_t r;
    asm("cvt.rna.tf32.f32 %0, %1;" : "=r"(r) : "f"(x));
    return __uint_as_float(r);
}
__device__ __forceinline__ uint32_t f2tf(float x) {
    uint32_t r;
    asm("cvt.rna.tf32.f32 %0, %1;" : "=r"(r) : "f"(x));
    return r;
}
__device__ __forceinline__ void cp16(uint32_t dst, const void* src, bool pred) {
    uint32_t sz = pred ? 16u : 0u;
    asm volatile("cp.async.cg.shared.global [%0], [%1], 16, %2;"
                 :: "r"(dst), "l"(src), "r"(sz));
}
#define CP_COMMIT() asm volatile("cp.async.commit_group;" ::: "memory")
#define CP_WAIT0()  asm volatile("cp.async.wait_group 0;" ::: "memory")

__device__ __forceinline__ void mma_tf32(float* c, const uint32_t* a,
                                         uint32_t b0, uint32_t b1) {
    asm volatile(
        "mma.sync.aligned.m16n8k8.row.col.f32.tf32.tf32.f32 "
        "{%0,%1,%2,%3}, {%4,%5,%6,%7}, {%8,%9}, {%0,%1,%2,%3};"
        : "+f"(c[0]), "+f"(c[1]), "+f"(c[2]), "+f"(c[3])
        : "r"(a[0]), "r"(a[1]), "r"(a[2]), "r"(a[3]), "r"(b0), "r"(b1));
}

__device__ __forceinline__ float gelu_exact(float v) {
    return 0.5f * v * (1.0f + erff(v * 0.70710678118654752f));
}

// ---------------- Weight transpose + tf32 rounding ----------------
// out[n*K + k] = round_tf32(in[k*N + n])
__global__ void transpose_tf32(const float* __restrict__ in, float* __restrict__ out,
                               int K, int N)
{
    __shared__ float tile[32][33];
    int kb = blockIdx.y * 32, nb = blockIdx.x * 32;
    int tx = threadIdx.x, ty = threadIdx.y;
    for (int i = ty; i < 32; i += 8) {
        int kk = kb + i, nn = nb + tx;
        tile[i][tx] = (kk < K && nn < N) ? in[(size_t)kk * N + nn] : 0.0f;
    }
    __syncthreads();
    for (int i = ty; i < 32; i += 8) {
        int nn = nb + i, kk = kb + tx;
        if (nn < N && kk < K) out[(size_t)nn * K + kk] = tf32r(tile[tx][i]);
    }
}

// ---------------- [SEP] position per batch row ----------------
__global__ void sep_kernel(const int* __restrict__ ids) {
    int b = threadIdx.x;
    if (b < Bc) {
        int s = Sc - 1;
        for (int i = 0; i < Sc; i++) {
            if (ids[b*Sc + i] == SEPc) { s = i; break; }
        }
        g_sep[b] = s;
    }
}

// ---------------- Embedding + LayerNorm ----------------
__global__ void embed_ln_kernel(const int* __restrict__ ids,
                                const float* __restrict__ we,
                                const float* __restrict__ pe,
                                const float* __restrict__ te,
                                const float* __restrict__ gg,
                                const float* __restrict__ bb)
{
    int row = blockIdx.x;
    int s   = row % Sc;
    int tid = threadIdx.x;
    __shared__ float buf[Hc];
    __shared__ float red[256];
    int id = ids[row];
    float lsum = 0.f;
    for (int j = tid; j < Hc; j += 256) {
        float val = we[(size_t)id*Hc + j] + pe[s*Hc + j] + te[j];
        buf[j] = val;
        lsum += val;
    }
    red[tid] = lsum; __syncthreads();
    for (int o = 128; o > 0; o >>= 1) { if (tid < o) red[tid] += red[tid+o]; __syncthreads(); }
    float mean = red[0] * (1.0f/Hc);
    __syncthreads();
    float lsq = 0.f;
    for (int j = tid; j < Hc; j += 256) { float d = buf[j]-mean; lsq += d*d; }
    red[tid] = lsq; __syncthreads();
    for (int o = 128; o > 0; o >>= 1) { if (tid < o) red[tid] += red[tid+o]; __syncthreads(); }
    float inv = rsqrtf(red[0]*(1.0f/Hc) + LN_EPS);
    for (int j = tid; j < Hc; j += 256)
        g_x[(size_t)row*Hc + j] = (buf[j]-mean)*inv*gg[j] + bb[j];
}

// ---------------- Residual add + LayerNorm (x = LN(x + t)) ----------------
__global__ void add_ln_kernel(float* __restrict__ x, const float* __restrict__ t,
                              const float* __restrict__ gg, const float* __restrict__ bb)
{
    int row = blockIdx.x;
    int tid = threadIdx.x;
    __shared__ float buf[Hc];
    __shared__ float red[256];
    float lsum = 0.f;
    for (int j = tid; j < Hc; j += 256) {
        float val = x[(size_t)row*Hc + j] + t[(size_t)row*Hc + j];
        buf[j] = val;
        lsum += val;
    }
    red[tid] = lsum; __syncthreads();
    for (int o = 128; o > 0; o >>= 1) { if (tid < o) red[tid] += red[tid+o]; __syncthreads(); }
    float mean = red[0] * (1.0f/Hc);
    __syncthreads();
    float lsq = 0.f;
    for (int j = tid; j < Hc; j += 256) { float d = buf[j]-mean; lsq += d*d; }
    red[tid] = lsq; __syncthreads();
    for (int o = 128; o > 0; o >>= 1) { if (tid < o) red[tid] += red[tid+o]; __syncthreads(); }
    float inv = rsqrtf(red[0]*(1.0f/Hc) + LN_EPS);
    for (int j = tid; j < Hc; j += 256)
        x[(size_t)row*Hc + j] = (buf[j]-mean)*inv*gg[j] + bb[j];
}

// ======================= mma.sync tf32 GEMM =======================
// C[M,N] = act(A[M,K] @ Bt[N,K]^T + bias)
// CTA tile 128x128, BK=32 floats, double-buffered cp.async.
// 8 warps: warp (wm = w&3, wn = w>>2) owns 32(M) x 64(N): 2 x 8 m16n8k8 frags.
// SMEM: A stages @0,@18432 ; B stages @36864,@55296 ; stride 36 floats (conflict-free frag loads).
#define GEMM_SMEM_BYTES 73728
#define ASZB 18432          // bytes per stage
#define ASZF 4608           // floats per stage (128*36)

template<int ACT>
__global__ __launch_bounds__(256)
void tc_gemm(const float* __restrict__ A, const float* __restrict__ Bt,
             const float* __restrict__ bias, float* __restrict__ C,
             int M, int N, int K)
{
    extern __shared__ __align__(16) char smraw[];
    float* sA = (float*)smraw;                    // 2 stages
    float* sB = (float*)(smraw + 2 * ASZB);       // 2 stages
    const uint32_t sbase = smem_to_u32(smraw);

    const int t    = threadIdx.x;
    const int lane = t & 31;
    const int w    = t >> 5;
    const int wm   = w & 3;      // 0..3 (M)
    const int wn   = w >> 2;     // 0..1 (N)
    const int m0   = blockIdx.y * 128;
    const int n0   = blockIdx.x * 128;
    const int nk   = K >> 5;

    float acc[2][8][4];
#pragma unroll
    for (int mt = 0; mt < 2; mt++)
#pragma unroll
        for (int nt = 0; nt < 8; nt++)
#pragma unroll
            for (int i = 0; i < 4; i++) acc[mt][nt][i] = 0.f;

    // per-thread load coords: idx = t + i*256 over 1024; row = idx>>3, q = idx&7
    auto load_stage = [&](int c) {
        const int s  = c & 1;
        const int k0 = c << 5;
        const uint32_t aB = sbase + (uint32_t)s * ASZB;
        const uint32_t bB = sbase + 2u * ASZB + (uint32_t)s * ASZB;
#pragma unroll
        for (int i = 0; i < 4; i++) {
            int idx = t + i * 256;
            int row = idx >> 3, q = idx & 7;
            cp16(aB + (uint32_t)(row * 36 + q * 4) * 4,
                 A + (size_t)(m0 + row) * K + k0 + q * 4, true);
            int nr = n0 + row;
            bool p = nr < N;
            int nrc = p ? nr : (N - 1);
            cp16(bB + (uint32_t)(row * 36 + q * 4) * 4,
                 Bt + (size_t)nrc * K + k0 + q * 4, p);
        }
        CP_COMMIT();
    };

    load_stage(0);
    for (int c = 0; c < nk; c++) {
        CP_WAIT0();
        __syncthreads();
        if (c + 1 < nk) load_stage(c + 1);

        const int s = c & 1;
        const float* sAx = sA + s * ASZF;
        const float* sBx = sB + s * ASZF;
#pragma unroll
        for (int ks = 0; ks < 4; ks++) {
            const int k = ks * 8 + (lane & 3);
            uint32_t af[2][4];
#pragma unroll
            for (int mt = 0; mt < 2; mt++) {
                const float* ap = sAx + (wm * 32 + mt * 16 + (lane >> 2)) * 36 + k;
                af[mt][0] = f2tf(ap[0]);
                af[mt][1] = f2tf(ap[8 * 36]);
                af[mt][2] = f2tf(ap[4]);
                af[mt][3] = f2tf(ap[8 * 36 + 4]);
            }
#pragma unroll
            for (int nt = 0; nt < 8; nt++) {
                const float* bp = sBx + (wn * 64 + nt * 8 + (lane >> 2)) * 36 + k;
                uint32_t b0 = __float_as_uint(bp[0]);
                uint32_t b1 = __float_as_uint(bp[4]);
                mma_tf32(acc[0][nt], af[0], b0, b1);
                mma_tf32(acc[1][nt], af[1], b0, b1);
            }
        }
        __syncthreads();
    }

    // Epilogue
#pragma unroll
    for (int mt = 0; mt < 2; mt++) {
        int rlo = m0 + wm * 32 + mt * 16 + (lane >> 2);
        int rhi = rlo + 8;
#pragma unroll
        for (int nt = 0; nt < 8; nt++) {
            int col = n0 + wn * 64 + nt * 8 + 2 * (lane & 3);
            if (col < N) {
                float b0v = bias[col], b1v = bias[col + 1];
                float v0 = acc[mt][nt][0] + b0v;
                float v1 = acc[mt][nt][1] + b1v;
                float v2 = acc[mt][nt][2] + b0v;
                float v3 = acc[mt][nt][3] + b1v;
                if (ACT == 1) {
                    v0 = gelu_exact(v0); v1 = gelu_exact(v1);
                    v2 = gelu_exact(v2); v3 = gelu_exact(v3);
                }
                float2 lo; lo.x = v0; lo.y = v1;
                float2 hi; hi.x = v2; hi.y = v3;
                *reinterpret_cast<float2*>(C + (size_t)rlo * N + col) = lo;
                *reinterpret_cast<float2*>(C + (size_t)rhi * N + col) = hi;
            }
        }
    }
}

// ======================= Tiled fused attention =======================
// Block = (b, h, 32-q tile), 256 threads.
// SMEM: sQ[32][65] @0 (8320B) | sKV @8320 (max 33792B) | sS[32][513] @42112 (65664B) | sInv @107776
#define ATTN_SMEM_BYTES 108032
#define SQ_OFF   0
#define SKV_OFF  8320
#define SS_OFF   42112
#define SINV_OFF 107776

__global__ __launch_bounds__(256, 1)
void attn2_kernel(const float* __restrict__ q, const float* __restrict__ k,
                  const float* __restrict__ v, float* __restrict__ ctx)
{
    extern __shared__ __align__(16) char sm[];
    float* sQ   = (float*)(sm + SQ_OFF);    // [32][65]
    float* sKV  = (float*)(sm + SKV_OFF);   // K: [128][65] ; V: [128][66]
    float* sS   = (float*)(sm + SS_OFF);    // [32][513]
    float* sInv = (float*)(sm + SINV_OFF);  // [32]

    const int t  = threadIdx.x;
    const int q0 = blockIdx.x * 32;
    const int h  = blockIdx.y;
    const int b  = blockIdx.z;
    const int sp = g_sep[b];

    // Load Q tile (32 rows x 64 d)
    for (int idx = t; idx < 32 * 16; idx += 256) {
        int qq = idx >> 4, fi = idx & 15;
        float4 vq = *reinterpret_cast<const float4*>(
            q + ((size_t)(b * Sc + q0 + qq) * Hc) + h * DHc + fi * 4);
        float* dst = sQ + qq * 65 + fi * 4;
        dst[0] = vq.x; dst[1] = vq.y; dst[2] = vq.z; dst[3] = vq.w;
    }
    __syncthreads();

    const int tq = t >> 5;   // 0..7  -> q rows 4*tq..4*tq+3
    const int tk = t & 31;   // 0..31 -> k cols tk+32j

    // ---- Scores: S = (Q K^T)*scale + mask ----
    for (int c = 0; c < 4; c++) {
        const int kbase = c * 128;
        for (int idx = t; idx < 128 * 16; idx += 256) {
            int kk = idx >> 4, fi = idx & 15;
            float4 vk = *reinterpret_cast<const float4*>(
                k + ((size_t)(b * Sc + kbase + kk) * Hc) + h * DHc + fi * 4);
            float* dst = sKV + kk * 65 + fi * 4;
            dst[0] = vk.x; dst[1] = vk.y; dst[2] = vk.z; dst[3] = vk.w;
        }
        __syncthreads();

        float accs[4][4];
#pragma unroll
        for (int i = 0; i < 4; i++)
#pragma unroll
            for (int j = 0; j < 4; j++) accs[i][j] = 0.f;

#pragma unroll 4
        for (int d = 0; d < 64; d++) {
            float qv[4], kv[4];
#pragma unroll
            for (int i = 0; i < 4; i++) qv[i] = sQ[(4 * tq + i) * 65 + d];
#pragma unroll
            for (int j = 0; j < 4; j++) kv[j] = sKV[(tk + 32 * j) * 65 + d];
#pragma unroll
            for (int i = 0; i < 4; i++)
#pragma unroll
                for (int j = 0; j < 4; j++)
                    accs[i][j] = fmaf(qv[i], kv[j], accs[i][j]);
        }
#pragma unroll
        for (int i = 0; i < 4; i++) {
            int qq = q0 + 4 * tq + i;
#pragma unroll
            for (int j = 0; j < 4; j++) {
                int kk2 = kbase + tk + 32 * j;
                float s = accs[i][j] * 0.125f;
                bool allowed = (kk2 <= qq) || (qq <= sp && kk2 <= sp);
                if (!allowed) s -= 1e4f;
                sS[(4 * tq + i) * 513 + kk2] = s;
            }
        }
        __syncthreads();
    }

    // ---- Softmax over each of 32 rows (8 threads / row) ----
    {
        const int r = t >> 3, sub = t & 7;
        float m = -3.4e38f;
        for (int j = sub; j < Sc; j += 8) m = fmaxf(m, sS[r * 513 + j]);
#pragma unroll
        for (int msk = 1; msk < 8; msk <<= 1)
            m = fmaxf(m, __shfl_xor_sync(0xffffffffu, m, msk));
        float sum = 0.f;
        for (int j = sub; j < Sc; j += 8) {
            float e = expf(sS[r * 513 + j] - m);
            sS[r * 513 + j] = e;
            sum += e;
        }
#pragma unroll
        for (int msk = 1; msk < 8; msk <<= 1)
            sum += __shfl_xor_sync(0xffffffffu, sum, msk);
        if (sub == 0) sInv[r] = 1.0f / sum;
    }
    __syncthreads();

    // ---- ctx = P @ V ----
    const int tq2 = t >> 5;   // 0..7  -> q rows 4*tq2..
    const int td  = t & 31;   // 0..31 -> d pair 2*td
    float cacc[4][2];
#pragma unroll
    for (int i = 0; i < 4; i++) { cacc[i][0] = 0.f; cacc[i][1] = 0.f; }

    for (int c = 0; c < 4; c++) {
        const int kbase = c * 128;
        for (int idx = t; idx < 128 * 16; idx += 256) {
            int kk = idx >> 4, fi = idx & 15;
            float4 vv = *reinterpret_cast<const float4*>(
                v + ((size_t)(b * Sc + kbase + kk) * Hc) + h * DHc + fi * 4);
            float* dst = sKV + kk * 66 + fi * 4;
            dst[0] = vv.x; dst[1] = vv.y; dst[2] = vv.z; dst[3] = vv.w;
        }
        __syncthreads();
#pragma unroll 4
        for (int kk = 0; kk < 128; kk++) {
            float2 vv = *reinterpret_cast<const float2*>(&sKV[kk * 66 + 2 * td]);
            float p0 = sS[(4 * tq2 + 0) * 513 + kbase + kk];
            float p1 = sS[(4 * tq2 + 1) * 513 + kbase + kk];
            float p2 = sS[(4 * tq2 + 2) * 513 + kbase + kk];
            float p3 = sS[(4 * tq2 + 3) * 513 + kbase + kk];
            cacc[0][0] = fmaf(p0, vv.x, cacc[0][0]); cacc[0][1] = fmaf(p0, vv.y, cacc[0][1]);
            cacc[1][0] = fmaf(p1, vv.x, cacc[1][0]); cacc[1][1] = fmaf(p1, vv.y, cacc[1][1]);
            cacc[2][0] = fmaf(p2, vv.x, cacc[2][0]); cacc[2][1] = fmaf(p2, vv.y, cacc[2][1]);
            cacc[3][0] = fmaf(p3, vv.x, cacc[3][0]); cacc[3][1] = fmaf(p3, vv.y, cacc[3][1]);
        }
        __syncthreads();
    }
#pragma unroll
    for (int i = 0; i < 4; i++) {
        int qq = q0 + 4 * tq2 + i;
        float inv = sInv[4 * tq2 + i];
        float2 o; o.x = cacc[i][0] * inv; o.y = cacc[i][1] * inv;
        *reinterpret_cast<float2*>(ctx + ((size_t)(b * Sc + qq) * Hc) + h * DHc + 2 * td) = o;
    }
}

// ---------------- Per-row log-softmax NLL ----------------
__global__ void row_loss_kernel(const int* __restrict__ labels)
{
    int row = blockIdx.x;
    int tid = threadIdx.x;
    const float* lr = g_logits + (size_t)row * Vc;
    __shared__ float red[256];

    float m = -3.4e38f;
    for (int j = tid; j < Vc; j += 256) m = fmaxf(m, lr[j]);
    red[tid] = m; __syncthreads();
    for (int o = 128; o > 0; o >>= 1) { if (tid < o) red[tid] = fmaxf(red[tid], red[tid+o]); __syncthreads(); }
    m = red[0];
    __syncthreads();

    float s = 0.f;
    for (int j = tid; j < Vc; j += 256) s += expf(lr[j] - m);
    red[tid] = s; __syncthreads();
    for (int o = 128; o > 0; o >>= 1) { if (tid < o) red[tid] += red[tid+o]; __syncthreads(); }

    if (tid == 0) {
        int lab = labels[row];
        if (lab >= 0) {
            g_nll[row]   = (m + logf(red[0])) - lr[lab];
            g_valid[row] = 1.0f;
        } else {
            g_nll[row]   = 0.0f;
            g_valid[row] = 0.0f;
        }
    }
}

// ---------------- Deterministic final reduction ----------------
__global__ void loss_reduce_kernel(float* __restrict__ out)
{
    __shared__ float rs[1024];
    __shared__ float rc[1024];
    int tid = threadIdx.x;
    float s = 0.f, c = 0.f;
    for (int i = tid; i < Mc; i += 1024) { s += g_nll[i]; c += g_valid[i]; }
    rs[tid] = s; rc[tid] = c; __syncthreads();
    for (int o = 512; o > 0; o >>= 1) {
        if (tid < o) { rs[tid] += rs[tid+o]; rc[tid] += rc[tid+o]; }
        __syncthreads();
    }
    if (tid == 0) out[0] = rs[0] / fmaxf(rc[0], 1.0f);
}

// ---------------- Host orchestration ----------------
static void run_tr(const float* in, float* out, int K, int N)
{
    dim3 g((N + 31) / 32, (K + 31) / 32);
    transpose_tf32<<<g, dim3(32, 8)>>>(in, out, K, N);
}

static void run_gemm(const float* A, const float* Bt, const float* bias, float* C,
                     int M, int N, int K, bool gelu)
{
    dim3 grid((N + 127) / 128, M / 128);
    if (gelu) tc_gemm<1><<<grid, 256, GEMM_SMEM_BYTES>>>(A, Bt, bias, C, M, N, K);
    else      tc_gemm<0><<<grid, 256, GEMM_SMEM_BYTES>>>(A, Bt, bias, C, M, N, K);
}

extern "C" void kernel_launch(void* const* d_in, const int* in_sizes, int n_in,
                              void* d_out, int out_size)
{
    (void)in_sizes; (void)n_in; (void)out_size;

    const int*   ids      = (const int*)  d_in[0];
    const int*   labels   = (const int*)  d_in[1];
    const float* word_emb = (const float*)d_in[2];
    const float* pos_emb  = (const float*)d_in[3];
    const float* type_emb = (const float*)d_in[4];
    const float* eg       = (const float*)d_in[5];
    const float* eb       = (const float*)d_in[6];
    const float* Wq       = (const float*)d_in[7];
    const float* bq       = (const float*)d_in[8];
    const float* Wk       = (const float*)d_in[9];
    const float* bk       = (const float*)d_in[10];
    const float* Wv       = (const float*)d_in[11];
    const float* bv       = (const float*)d_in[12];
    const float* Wo       = (const float*)d_in[13];
    const float* bo       = (const float*)d_in[14];
    const float* l1g      = (const float*)d_in[15];
    const float* l1b      = (const float*)d_in[16];
    const float* Wi       = (const float*)d_in[17];
    const float* bi       = (const float*)d_in[18];
    const float* Wd       = (const float*)d_in[19];
    const float* bd       = (const float*)d_in[20];
    const float* l2g      = (const float*)d_in[21];
    const float* l2b      = (const float*)d_in[22];
    const float* Wc       = (const float*)d_in[23];
    const float* bc       = (const float*)d_in[24];

    cudaFuncSetAttribute(tc_gemm<0>, cudaFuncAttributeMaxDynamicSharedMemorySize, GEMM_SMEM_BYTES);
    cudaFuncSetAttribute(tc_gemm<1>, cudaFuncAttributeMaxDynamicSharedMemorySize, GEMM_SMEM_BYTES);
    cudaFuncSetAttribute(attn2_kernel, cudaFuncAttributeMaxDynamicSharedMemorySize, ATTN_SMEM_BYTES);

    void* p;
    cudaGetSymbolAddress(&p, g_x);     float* px    = (float*)p;
    cudaGetSymbolAddress(&p, g_q);     float* pq    = (float*)p;
    cudaGetSymbolAddress(&p, g_k);     float* pk    = (float*)p;
    cudaGetSymbolAddress(&p, g_v);     float* pv    = (float*)p;
    cudaGetSymbolAddress(&p, g_ctx);   float* pctx  = (float*)p;
    cudaGetSymbolAddress(&p, g_proj);  float* pproj = (float*)p;
    cudaGetSymbolAddress(&p, g_ffn);   float* pffn  = (float*)p;
    cudaGetSymbolAddress(&p, g_logits);float* plog  = (float*)p;
    cudaGetSymbolAddress(&p, g_WqT);   float* pWqT  = (float*)p;
    cudaGetSymbolAddress(&p, g_WkT);   float* pWkT  = (float*)p;
    cudaGetSymbolAddress(&p, g_WvT);   float* pWvT  = (float*)p;
    cudaGetSymbolAddress(&p, g_WoT);   float* pWoT  = (float*)p;
    cudaGetSymbolAddress(&p, g_WiT);   float* pWiT  = (float*)p;
    cudaGetSymbolAddress(&p, g_WdT);   float* pWdT  = (float*)p;
    cudaGetSymbolAddress(&p, g_WcT);   float* pWcT  = (float*)p;

    // Pre-transpose all weights to N-major (K-contiguous), rounded to tf32
    for (int l = 0; l < Lc; l++) {
        const size_t oHH = (size_t)l * Hc * Hc;
        run_tr(Wq + oHH, pWqT + oHH, Hc, Hc);
        run_tr(Wk + oHH, pWkT + oHH, Hc, Hc);
        run_tr(Wv + oHH, pWvT + oHH, Hc, Hc);
        run_tr(Wo + oHH, pWoT + oHH, Hc, Hc);
        run_tr(Wi + (size_t)l*Hc*FFc, pWiT + (size_t)l*FFc*Hc, Hc, FFc);
        run_tr(Wd + (size_t)l*FFc*Hc, pWdT + (size_t)l*Hc*FFc, FFc, Hc);
    }
    run_tr(Wc, pWcT, Hc, Vc);

    sep_kernel<<<1, 32>>>(ids);
    embed_ln_kernel<<<Mc, 256>>>(ids, word_emb, pos_emb, type_emb, eg, eb);

    for (int l = 0; l < Lc; l++) {
        const size_t wHH = (size_t)l * Hc * Hc;
        run_gemm(px,   pWqT + wHH, bq + (size_t)l*Hc, pq, Mc, Hc, Hc, false);
        run_gemm(px,   pWkT + wHH, bk + (size_t)l*Hc, pk, Mc, Hc, Hc, false);
        run_gemm(px,   pWvT + wHH, bv + (size_t)l*Hc, pv, Mc, Hc, Hc, false);
        attn2_kernel<<<dim3(Sc/32, NHc, Bc), 256, ATTN_SMEM_BYTES>>>(pq, pk, pv, pctx);
        run_gemm(pctx, pWoT + wHH, bo + (size_t)l*Hc, pproj, Mc, Hc, Hc, false);
        add_ln_kernel<<<Mc, 256>>>(px, pproj, l1g + (size_t)l*Hc, l1b + (size_t)l*Hc);
        run_gemm(px,   pWiT + (size_t)l*FFc*Hc, bi + (size_t)l*FFc, pffn, Mc, FFc, Hc, true);
        run_gemm(pffn, pWdT + (size_t)l*Hc*FFc, bd + (size_t)l*Hc, pproj, Mc, Hc, FFc, false);
        add_ln_kernel<<<Mc, 256>>>(px, pproj, l2g + (size_t)l*Hc, l2b + (size_t)l*Hc);
    }

    run_gemm(px, pWcT, bc, plog, Mc, Vc, Hc, false);
    row_loss_kernel<<<Mc, 256>>>(labels);
    loss_reduce_kernel<<<1, 1024>>>((float*)d_out);
}

// round 4
// speedup vs baseline: 5.5647x; 1.3233x over previous
#include <cuda_runtime.h>
#include <cuda_bf16.h>
#include <math.h>
#include <stdint.h>

// Problem constants
#define Lc 12
#define Hc 768
#define NHc 12
#define DHc 64
#define FFc 3072
#define Vc 21128
#define Sc 512
#define Bc 8
#define Mc (Bc*Sc)          // 4096 tokens
#define SEPc 102
#define LN_EPS 1e-12f

typedef __nv_bfloat16 bf16;
typedef __nv_bfloat162 bf162;

// ---------------- Device scratch (static; no runtime allocation) ----------------
__device__ float g_x[Mc*Hc];          // fp32 residual stream
__device__ bf16  g_xb[Mc*Hc];         // bf16 copy of x (GEMM A operand)
__device__ float g_q[Mc*Hc];
__device__ float g_k[Mc*Hc];
__device__ float g_v[Mc*Hc];
__device__ bf16  g_ctxb[Mc*Hc];       // attention output (bf16, feeds Wo)
__device__ float g_proj[Mc*Hc];
__device__ bf16  g_ffnb[(size_t)Mc*FFc];  // GELU output (bf16, feeds Wd)
__device__ float g_logits[(size_t)Mc*Vc];
__device__ float g_nll[Mc];
__device__ float g_valid[Mc];
__device__ int   g_sep[Bc];
// Transposed (N-major, K-contiguous) bf16 weights
__device__ bf16 g_WqT[Lc*Hc*Hc];
__device__ bf16 g_WkT[Lc*Hc*Hc];
__device__ bf16 g_WvT[Lc*Hc*Hc];
__device__ bf16 g_WoT[Lc*Hc*Hc];
__device__ bf16 g_WiT[(size_t)Lc*FFc*Hc];
__device__ bf16 g_WdT[(size_t)Lc*Hc*FFc];
__device__ bf16 g_WcT[(size_t)Vc*Hc];

// ---------------- small PTX helpers (compute_103-safe) ----------------
__device__ __forceinline__ uint32_t smem_to_u32(const void* smem_ptr) {
    uint32_t addr;
    asm("{ .reg .u64 tmp; cvta.to.shared.u64 tmp, %1; cvt.u32.u64 %0, tmp; }"
        : "=r"(addr) : "l"(smem_ptr));
    return addr;
}
__device__ __forceinline__ void cp16(uint32_t dst, const void* src, bool pred) {
    uint32_t sz = pred ? 16u : 0u;
    asm volatile("cp.async.cg.shared.global [%0], [%1], 16, %2;"
                 :: "r"(dst), "l"(src), "r"(sz));
}
#define CP_COMMIT() asm volatile("cp.async.commit_group;" ::: "memory")
#define CP_WAIT0()  asm volatile("cp.async.wait_group 0;" ::: "memory")

__device__ __forceinline__ void mma_bf16(float* c, const uint32_t* a,
                                         uint32_t b0, uint32_t b1) {
    asm volatile(
        "mma.sync.aligned.m16n8k16.row.col.f32.bf16.bf16.f32 "
        "{%0,%1,%2,%3}, {%4,%5,%6,%7}, {%8,%9}, {%0,%1,%2,%3};"
        : "+f"(c[0]), "+f"(c[1]), "+f"(c[2]), "+f"(c[3])
        : "r"(a[0]), "r"(a[1]), "r"(a[2]), "r"(a[3]), "r"(b0), "r"(b1));
}

__device__ __forceinline__ float gelu_exact(float v) {
    return 0.5f * v * (1.0f + erff(v * 0.70710678118654752f));
}

// ---------------- Weight transpose + bf16 conversion ----------------
// out[n*K + k] = bf16(in[k*N + n])
__global__ void transpose_bf16(const float* __restrict__ in, bf16* __restrict__ out,
                               int K, int N)
{
    __shared__ float tile[32][33];
    int kb = blockIdx.y * 32, nb = blockIdx.x * 32;
    int tx = threadIdx.x, ty = threadIdx.y;
    for (int i = ty; i < 32; i += 8) {
        int kk = kb + i, nn = nb + tx;
        tile[i][tx] = (kk < K && nn < N) ? in[(size_t)kk * N + nn] : 0.0f;
    }
    __syncthreads();
    for (int i = ty; i < 32; i += 8) {
        int nn = nb + i, kk = kb + tx;
        if (nn < N && kk < K) out[(size_t)nn * K + kk] = __float2bfloat16_rn(tile[tx][i]);
    }
}

// ---------------- [SEP] position per batch row ----------------
__global__ void sep_kernel(const int* __restrict__ ids) {
    int b = threadIdx.x;
    if (b < Bc) {
        int s = Sc - 1;
        for (int i = 0; i < Sc; i++) {
            if (ids[b*Sc + i] == SEPc) { s = i; break; }
        }
        g_sep[b] = s;
    }
}

// ---------------- Embedding + LayerNorm (dual fp32 + bf16 output) ----------------
__global__ void embed_ln_kernel(const int* __restrict__ ids,
                                const float* __restrict__ we,
                                const float* __restrict__ pe,
                                const float* __restrict__ te,
                                const float* __restrict__ gg,
                                const float* __restrict__ bb)
{
    int row = blockIdx.x;
    int s   = row % Sc;
    int tid = threadIdx.x;
    __shared__ float buf[Hc];
    __shared__ float red[256];
    int id = ids[row];
    float lsum = 0.f;
    for (int j = tid; j < Hc; j += 256) {
        float val = we[(size_t)id*Hc + j] + pe[s*Hc + j] + te[j];
        buf[j] = val;
        lsum += val;
    }
    red[tid] = lsum; __syncthreads();
    for (int o = 128; o > 0; o >>= 1) { if (tid < o) red[tid] += red[tid+o]; __syncthreads(); }
    float mean = red[0] * (1.0f/Hc);
    __syncthreads();
    float lsq = 0.f;
    for (int j = tid; j < Hc; j += 256) { float d = buf[j]-mean; lsq += d*d; }
    red[tid] = lsq; __syncthreads();
    for (int o = 128; o > 0; o >>= 1) { if (tid < o) red[tid] += red[tid+o]; __syncthreads(); }
    float inv = rsqrtf(red[0]*(1.0f/Hc) + LN_EPS);
    for (int j = tid; j < Hc; j += 256) {
        float o = (buf[j]-mean)*inv*gg[j] + bb[j];
        g_x[(size_t)row*Hc + j]  = o;
        g_xb[(size_t)row*Hc + j] = __float2bfloat16_rn(o);
    }
}

// ---------------- Residual add + LayerNorm (x = LN(x + t)), dual output ----------------
__global__ void add_ln_kernel(float* __restrict__ x, bf16* __restrict__ xb,
                              const float* __restrict__ t,
                              const float* __restrict__ gg, const float* __restrict__ bb)
{
    int row = blockIdx.x;
    int tid = threadIdx.x;
    __shared__ float buf[Hc];
    __shared__ float red[256];
    float lsum = 0.f;
    for (int j = tid; j < Hc; j += 256) {
        float val = x[(size_t)row*Hc + j] + t[(size_t)row*Hc + j];
        buf[j] = val;
        lsum += val;
    }
    red[tid] = lsum; __syncthreads();
    for (int o = 128; o > 0; o >>= 1) { if (tid < o) red[tid] += red[tid+o]; __syncthreads(); }
    float mean = red[0] * (1.0f/Hc);
    __syncthreads();
    float lsq = 0.f;
    for (int j = tid; j < Hc; j += 256) { float d = buf[j]-mean; lsq += d*d; }
    red[tid] = lsq; __syncthreads();
    for (int o = 128; o > 0; o >>= 1) { if (tid < o) red[tid] += red[tid+o]; __syncthreads(); }
    float inv = rsqrtf(red[0]*(1.0f/Hc) + LN_EPS);
    for (int j = tid; j < Hc; j += 256) {
        float o = (buf[j]-mean)*inv*gg[j] + bb[j];
        x[(size_t)row*Hc + j]  = o;
        xb[(size_t)row*Hc + j] = __float2bfloat16_rn(o);
    }
}

// ======================= mma.sync bf16 GEMM =======================
// C[M,N] = act(A[M,K] @ Bt[N,K]^T + bias); A, Bt in bf16; acc fp32.
// CTA tile 128x128, BK=32 (bf16), double-buffered cp.async.
// 8 warps: warp (wm = w&3, wn = w>>2) owns 32(M) x 64(N): 2x8 m16n8k16 frags.
// SMEM rows stride 40 halfwords (80B) -> conflict-free 32-bit fragment LDS.
#define STG_HW 5120            // halfwords per stage (128*40)
#define STG_B  10240           // bytes per stage
#define GEMM_SMEM_BYTES 40960  // 4 stages total (A0,A1,B0,B1)

template<int ACT, int OUTBF>
__global__ __launch_bounds__(256)
void tc_gemm(const bf16* __restrict__ A, const bf16* __restrict__ Bt,
             const float* __restrict__ bias, void* __restrict__ Cv,
             int M, int N, int K)
{
    extern __shared__ __align__(16) char smraw[];
    const uint32_t sbase = smem_to_u32(smraw);
    uint16_t* sH = (uint16_t*)smraw;

    const int t    = threadIdx.x;
    const int lane = t & 31;
    const int w    = t >> 5;
    const int wm   = w & 3;      // 0..3 (M)
    const int wn   = w >> 2;     // 0..1 (N)
    const int m0   = blockIdx.y * 128;
    const int n0   = blockIdx.x * 128;
    const int nk   = K >> 5;

    float acc[2][8][4];
#pragma unroll
    for (int mt = 0; mt < 2; mt++)
#pragma unroll
        for (int nt = 0; nt < 8; nt++)
#pragma unroll
            for (int i = 0; i < 4; i++) acc[mt][nt][i] = 0.f;

    // loader: 512 16B chunks per operand per stage; 2 per thread
    auto load_stage = [&](int c) {
        const int s  = c & 1;
        const int k0 = c << 5;
        const uint32_t aB = sbase + (uint32_t)s * STG_B;
        const uint32_t bB = sbase + 2u * STG_B + (uint32_t)s * STG_B;
#pragma unroll
        for (int i = 0; i < 2; i++) {
            int idx = t + i * 256;
            int row = idx >> 2, q = idx & 3;
            cp16(aB + (uint32_t)(row * 80 + q * 16),
                 A + (size_t)(m0 + row) * K + k0 + q * 8, true);
            int nr = n0 + row;
            bool p = nr < N;
            int nrc = p ? nr : 0;
            cp16(bB + (uint32_t)(row * 80 + q * 16),
                 Bt + (size_t)nrc * K + k0 + q * 8, p);
        }
        CP_COMMIT();
    };

    const int lrow = lane >> 2;       // 0..7
    const int lk   = 2 * (lane & 3);  // 0,2,4,6

    load_stage(0);
    for (int c = 0; c < nk; c++) {
        CP_WAIT0();
        __syncthreads();
        if (c + 1 < nk) load_stage(c + 1);

        const int s = c & 1;
        const uint16_t* sAx = sH + s * STG_HW;
        const uint16_t* sBx = sH + 2 * STG_HW + s * STG_HW;
#pragma unroll
        for (int ks = 0; ks < 2; ks++) {
            const int kb = ks * 16;
            uint32_t af[2][4];
#pragma unroll
            for (int mt = 0; mt < 2; mt++) {
                const uint16_t* ap = sAx + (wm * 32 + mt * 16 + lrow) * 40 + kb + lk;
                af[mt][0] = *reinterpret_cast<const uint32_t*>(ap);
                af[mt][1] = *reinterpret_cast<const uint32_t*>(ap + 8 * 40);
                af[mt][2] = *reinterpret_cast<const uint32_t*>(ap + 8);
                af[mt][3] = *reinterpret_cast<const uint32_t*>(ap + 8 * 40 + 8);
            }
#pragma unroll
            for (int nt = 0; nt < 8; nt++) {
                const uint16_t* bp = sBx + (wn * 64 + nt * 8 + lrow) * 40 + kb + lk;
                uint32_t b0 = *reinterpret_cast<const uint32_t*>(bp);
                uint32_t b1 = *reinterpret_cast<const uint32_t*>(bp + 8);
                mma_bf16(acc[0][nt], af[0], b0, b1);
                mma_bf16(acc[1][nt], af[1], b0, b1);
            }
        }
        __syncthreads();
    }

    // Epilogue
    float* Cf = (float*)Cv;
    bf16*  Cb = (bf16*)Cv;
#pragma unroll
    for (int mt = 0; mt < 2; mt++) {
        int rlo = m0 + wm * 32 + mt * 16 + lrow;
        int rhi = rlo + 8;
#pragma unroll
        for (int nt = 0; nt < 8; nt++) {
            int col = n0 + wn * 64 + nt * 8 + lk;
            if (col < N) {
                float b0v = bias[col], b1v = bias[col + 1];
                float v0 = acc[mt][nt][0] + b0v;
                float v1 = acc[mt][nt][1] + b1v;
                float v2 = acc[mt][nt][2] + b0v;
                float v3 = acc[mt][nt][3] + b1v;
                if (ACT == 1) {
                    v0 = gelu_exact(v0); v1 = gelu_exact(v1);
                    v2 = gelu_exact(v2); v3 = gelu_exact(v3);
                }
                if (OUTBF) {
                    bf162 lo; lo.x = __float2bfloat16_rn(v0); lo.y = __float2bfloat16_rn(v1);
                    bf162 hi; hi.x = __float2bfloat16_rn(v2); hi.y = __float2bfloat16_rn(v3);
                    *reinterpret_cast<bf162*>(Cb + (size_t)rlo * N + col) = lo;
                    *reinterpret_cast<bf162*>(Cb + (size_t)rhi * N + col) = hi;
                } else {
                    float2 lo; lo.x = v0; lo.y = v1;
                    float2 hi; hi.x = v2; hi.y = v3;
                    *reinterpret_cast<float2*>(Cf + (size_t)rlo * N + col) = lo;
                    *reinterpret_cast<float2*>(Cf + (size_t)rhi * N + col) = hi;
                }
            }
        }
    }
}

// ======================= Tiled fused attention (fp32 math, bf16 ctx out) =======================
// Block = (b, h, 32-q tile), 256 threads.
// SMEM: sQ[32][65] @0 (8320B) | sKV @8320 (max 33792B) | sS[32][513] @42112 (65664B) | sInv @107776
#define ATTN_SMEM_BYTES 108032
#define SQ_OFF   0
#define SKV_OFF  8320
#define SS_OFF   42112
#define SINV_OFF 107776

__global__ __launch_bounds__(256, 1)
void attn2_kernel(const float* __restrict__ q, const float* __restrict__ k,
                  const float* __restrict__ v, bf16* __restrict__ ctx)
{
    extern __shared__ __align__(16) char sm[];
    float* sQ   = (float*)(sm + SQ_OFF);    // [32][65]
    float* sKV  = (float*)(sm + SKV_OFF);   // K: [128][65] ; V: [128][66]
    float* sS   = (float*)(sm + SS_OFF);    // [32][513]
    float* sInv = (float*)(sm + SINV_OFF);  // [32]

    const int t  = threadIdx.x;
    const int q0 = blockIdx.x * 32;
    const int h  = blockIdx.y;
    const int b  = blockIdx.z;
    const int sp = g_sep[b];

    // Load Q tile (32 rows x 64 d)
    for (int idx = t; idx < 32 * 16; idx += 256) {
        int qq = idx >> 4, fi = idx & 15;
        float4 vq = *reinterpret_cast<const float4*>(
            q + ((size_t)(b * Sc + q0 + qq) * Hc) + h * DHc + fi * 4);
        float* dst = sQ + qq * 65 + fi * 4;
        dst[0] = vq.x; dst[1] = vq.y; dst[2] = vq.z; dst[3] = vq.w;
    }
    __syncthreads();

    const int tq = t >> 5;   // 0..7  -> q rows 4*tq..4*tq+3
    const int tk = t & 31;   // 0..31 -> k cols tk+32j

    // ---- Scores: S = (Q K^T)*scale + mask ----
    for (int c = 0; c < 4; c++) {
        const int kbase = c * 128;
        for (int idx = t; idx < 128 * 16; idx += 256) {
            int kk = idx >> 4, fi = idx & 15;
            float4 vk = *reinterpret_cast<const float4*>(
                k + ((size_t)(b * Sc + kbase + kk) * Hc) + h * DHc + fi * 4);
            float* dst = sKV + kk * 65 + fi * 4;
            dst[0] = vk.x; dst[1] = vk.y; dst[2] = vk.z; dst[3] = vk.w;
        }
        __syncthreads();

        float accs[4][4];
#pragma unroll
        for (int i = 0; i < 4; i++)
#pragma unroll
            for (int j = 0; j < 4; j++) accs[i][j] = 0.f;

#pragma unroll 4
        for (int d = 0; d < 64; d++) {
            float qv[4], kv[4];
#pragma unroll
            for (int i = 0; i < 4; i++) qv[i] = sQ[(4 * tq + i) * 65 + d];
#pragma unroll
            for (int j = 0; j < 4; j++) kv[j] = sKV[(tk + 32 * j) * 65 + d];
#pragma unroll
            for (int i = 0; i < 4; i++)
#pragma unroll
                for (int j = 0; j < 4; j++)
                    accs[i][j] = fmaf(qv[i], kv[j], accs[i][j]);
        }
#pragma unroll
        for (int i = 0; i < 4; i++) {
            int qq = q0 + 4 * tq + i;
#pragma unroll
            for (int j = 0; j < 4; j++) {
                int kk2 = kbase + tk + 32 * j;
                float s = accs[i][j] * 0.125f;
                bool allowed = (kk2 <= qq) || (qq <= sp && kk2 <= sp);
                if (!allowed) s -= 1e4f;
                sS[(4 * tq + i) * 513 + kk2] = s;
            }
        }
        __syncthreads();
    }

    // ---- Softmax over each of 32 rows (8 threads / row) ----
    {
        const int r = t >> 3, sub = t & 7;
        float m = -3.4e38f;
        for (int j = sub; j < Sc; j += 8) m = fmaxf(m, sS[r * 513 + j]);
#pragma unroll
        for (int msk = 1; msk < 8; msk <<= 1)
            m = fmaxf(m, __shfl_xor_sync(0xffffffffu, m, msk));
        float sum = 0.f;
        for (int j = sub; j < Sc; j += 8) {
            float e = expf(sS[r * 513 + j] - m);
            sS[r * 513 + j] = e;
            sum += e;
        }
#pragma unroll
        for (int msk = 1; msk < 8; msk <<= 1)
            sum += __shfl_xor_sync(0xffffffffu, sum, msk);
        if (sub == 0) sInv[r] = 1.0f / sum;
    }
    __syncthreads();

    // ---- ctx = P @ V ----
    const int tq2 = t >> 5;   // 0..7  -> q rows 4*tq2..
    const int td  = t & 31;   // 0..31 -> d pair 2*td
    float cacc[4][2];
#pragma unroll
    for (int i = 0; i < 4; i++) { cacc[i][0] = 0.f; cacc[i][1] = 0.f; }

    for (int c = 0; c < 4; c++) {
        const int kbase = c * 128;
        for (int idx = t; idx < 128 * 16; idx += 256) {
            int kk = idx >> 4, fi = idx & 15;
            float4 vv = *reinterpret_cast<const float4*>(
                v + ((size_t)(b * Sc + kbase + kk) * Hc) + h * DHc + fi * 4);
            float* dst = sKV + kk * 66 + fi * 4;
            dst[0] = vv.x; dst[1] = vv.y; dst[2] = vv.z; dst[3] = vv.w;
        }
        __syncthreads();
#pragma unroll 4
        for (int kk = 0; kk < 128; kk++) {
            float2 vv = *reinterpret_cast<const float2*>(&sKV[kk * 66 + 2 * td]);
            float p0 = sS[(4 * tq2 + 0) * 513 + kbase + kk];
            float p1 = sS[(4 * tq2 + 1) * 513 + kbase + kk];
            float p2 = sS[(4 * tq2 + 2) * 513 + kbase + kk];
            float p3 = sS[(4 * tq2 + 3) * 513 + kbase + kk];
            cacc[0][0] = fmaf(p0, vv.x, cacc[0][0]); cacc[0][1] = fmaf(p0, vv.y, cacc[0][1]);
            cacc[1][0] = fmaf(p1, vv.x, cacc[1][0]); cacc[1][1] = fmaf(p1, vv.y, cacc[1][1]);
            cacc[2][0] = fmaf(p2, vv.x, cacc[2][0]); cacc[2][1] = fmaf(p2, vv.y, cacc[2][1]);
            cacc[3][0] = fmaf(p3, vv.x, cacc[3][0]); cacc[3][1] = fmaf(p3, vv.y, cacc[3][1]);
        }
        __syncthreads();
    }
#pragma unroll
    for (int i = 0; i < 4; i++) {
        int qq = q0 + 4 * tq2 + i;
        float inv = sInv[4 * tq2 + i];
        bf162 o;
        o.x = __float2bfloat16_rn(cacc[i][0] * inv);
        o.y = __float2bfloat16_rn(cacc[i][1] * inv);
        *reinterpret_cast<bf162*>(ctx + ((size_t)(b * Sc + qq) * Hc) + h * DHc + 2 * td) = o;
    }
}

// ---------------- Per-row log-softmax NLL ----------------
__global__ void row_loss_kernel(const int* __restrict__ labels)
{
    int row = blockIdx.x;
    int tid = threadIdx.x;
    const float* lr = g_logits + (size_t)row * Vc;
    __shared__ float red[256];

    float m = -3.4e38f;
    for (int j = tid; j < Vc; j += 256) m = fmaxf(m, lr[j]);
    red[tid] = m; __syncthreads();
    for (int o = 128; o > 0; o >>= 1) { if (tid < o) red[tid] = fmaxf(red[tid], red[tid+o]); __syncthreads(); }
    m = red[0];
    __syncthreads();

    float s = 0.f;
    for (int j = tid; j < Vc; j += 256) s += expf(lr[j] - m);
    red[tid] = s; __syncthreads();
    for (int o = 128; o > 0; o >>= 1) { if (tid < o) red[tid] += red[tid+o]; __syncthreads(); }

    if (tid == 0) {
        int lab = labels[row];
        if (lab >= 0) {
            g_nll[row]   = (m + logf(red[0])) - lr[lab];
            g_valid[row] = 1.0f;
        } else {
            g_nll[row]   = 0.0f;
            g_valid[row] = 0.0f;
        }
    }
}

// ---------------- Deterministic final reduction ----------------
__global__ void loss_reduce_kernel(float* __restrict__ out)
{
    __shared__ float rs[1024];
    __shared__ float rc[1024];
    int tid = threadIdx.x;
    float s = 0.f, c = 0.f;
    for (int i = tid; i < Mc; i += 1024) { s += g_nll[i]; c += g_valid[i]; }
    rs[tid] = s; rc[tid] = c; __syncthreads();
    for (int o = 512; o > 0; o >>= 1) {
        if (tid < o) { rs[tid] += rs[tid+o]; rc[tid] += rc[tid+o]; }
        __syncthreads();
    }
    if (tid == 0) out[0] = rs[0] / fmaxf(rc[0], 1.0f);
}

// ---------------- Host orchestration ----------------
static void run_tr(const float* in, bf16* out, int K, int N)
{
    dim3 g((N + 31) / 32, (K + 31) / 32);
    transpose_bf16<<<g, dim3(32, 8)>>>(in, out, K, N);
}

template<int ACT, int OUTBF>
static void run_gemm_t(const bf16* A, const bf16* Bt, const float* bias, void* C,
                       int M, int N, int K)
{
    dim3 grid((N + 127) / 128, M / 128);
    tc_gemm<ACT, OUTBF><<<grid, 256, GEMM_SMEM_BYTES>>>(A, Bt, bias, C, M, N, K);
}

extern "C" void kernel_launch(void* const* d_in, const int* in_sizes, int n_in,
                              void* d_out, int out_size)
{
    (void)in_sizes; (void)n_in; (void)out_size;

    const int*   ids      = (const int*)  d_in[0];
    const int*   labels   = (const int*)  d_in[1];
    const float* word_emb = (const float*)d_in[2];
    const float* pos_emb  = (const float*)d_in[3];
    const float* type_emb = (const float*)d_in[4];
    const float* eg       = (const float*)d_in[5];
    const float* eb       = (const float*)d_in[6];
    const float* Wq       = (const float*)d_in[7];
    const float* bq       = (const float*)d_in[8];
    const float* Wk       = (const float*)d_in[9];
    const float* bk       = (const float*)d_in[10];
    const float* Wv       = (const float*)d_in[11];
    const float* bv       = (const float*)d_in[12];
    const float* Wo       = (const float*)d_in[13];
    const float* bo       = (const float*)d_in[14];
    const float* l1g      = (const float*)d_in[15];
    const float* l1b      = (const float*)d_in[16];
    const float* Wi       = (const float*)d_in[17];
    const float* bi       = (const float*)d_in[18];
    const float* Wd       = (const float*)d_in[19];
    const float* bd       = (const float*)d_in[20];
    const float* l2g      = (const float*)d_in[21];
    const float* l2b      = (const float*)d_in[22];
    const float* Wc       = (const float*)d_in[23];
    const float* bc       = (const float*)d_in[24];

    cudaFuncSetAttribute(attn2_kernel, cudaFuncAttributeMaxDynamicSharedMemorySize, ATTN_SMEM_BYTES);

    void* p;
    cudaGetSymbolAddress(&p, g_x);     float* px    = (float*)p;
    cudaGetSymbolAddress(&p, g_xb);    bf16*  pxb   = (bf16*)p;
    cudaGetSymbolAddress(&p, g_q);     float* pq    = (float*)p;
    cudaGetSymbolAddress(&p, g_k);     float* pk    = (float*)p;
    cudaGetSymbolAddress(&p, g_v);     float* pv    = (float*)p;
    cudaGetSymbolAddress(&p, g_ctxb);  bf16*  pctxb = (bf16*)p;
    cudaGetSymbolAddress(&p, g_proj);  float* pproj = (float*)p;
    cudaGetSymbolAddress(&p, g_ffnb);  bf16*  pffnb = (bf16*)p;
    cudaGetSymbolAddress(&p, g_logits);float* plog  = (float*)p;
    cudaGetSymbolAddress(&p, g_WqT);   bf16*  pWqT  = (bf16*)p;
    cudaGetSymbolAddress(&p, g_WkT);   bf16*  pWkT  = (bf16*)p;
    cudaGetSymbolAddress(&p, g_WvT);   bf16*  pWvT  = (bf16*)p;
    cudaGetSymbolAddress(&p, g_WoT);   bf16*  pWoT  = (bf16*)p;
    cudaGetSymbolAddress(&p, g_WiT);   bf16*  pWiT  = (bf16*)p;
    cudaGetSymbolAddress(&p, g_WdT);   bf16*  pWdT  = (bf16*)p;
    cudaGetSymbolAddress(&p, g_WcT);   bf16*  pWcT  = (bf16*)p;

    // Pre-transpose all weights to N-major (K-contiguous) bf16
    for (int l = 0; l < Lc; l++) {
        const size_t oHH = (size_t)l * Hc * Hc;
        run_tr(Wq + oHH, pWqT + oHH, Hc, Hc);
        run_tr(Wk + oHH, pWkT + oHH, Hc, Hc);
        run_tr(Wv + oHH, pWvT + oHH, Hc, Hc);
        run_tr(Wo + oHH, pWoT + oHH, Hc, Hc);
        run_tr(Wi + (size_t)l*Hc*FFc, pWiT + (size_t)l*FFc*Hc, Hc, FFc);
        run_tr(Wd + (size_t)l*FFc*Hc, pWdT + (size_t)l*Hc*FFc, FFc, Hc);
    }
    run_tr(Wc, pWcT, Hc, Vc);

    sep_kernel<<<1, 32>>>(ids);
    embed_ln_kernel<<<Mc, 256>>>(ids, word_emb, pos_emb, type_emb, eg, eb);

    for (int l = 0; l < Lc; l++) {
        const size_t wHH = (size_t)l * Hc * Hc;
        run_gemm_t<0,0>(pxb,   pWqT + wHH, bq + (size_t)l*Hc, pq, Mc, Hc, Hc);
        run_gemm_t<0,0>(pxb,   pWkT + wHH, bk + (size_t)l*Hc, pk, Mc, Hc, Hc);
        run_gemm_t<0,0>(pxb,   pWvT + wHH, bv + (size_t)l*Hc, pv, Mc, Hc, Hc);
        attn2_kernel<<<dim3(Sc/32, NHc, Bc), 256, ATTN_SMEM_BYTES>>>(pq, pk, pv, pctxb);
        run_gemm_t<0,0>(pctxb, pWoT + wHH, bo + (size_t)l*Hc, pproj, Mc, Hc, Hc);
        add_ln_kernel<<<Mc, 256>>>(px, pxb, pproj, l1g + (size_t)l*Hc, l1b + (size_t)l*Hc);
        run_gemm_t<1,1>(pxb,   pWiT + (size_t)l*FFc*Hc, bi + (size_t)l*FFc, pffnb, Mc, FFc, Hc);
        run_gemm_t<0,0>(pffnb, pWdT + (size_t)l*Hc*FFc, bd + (size_t)l*Hc, pproj, Mc, Hc, FFc);
        add_ln_kernel<<<Mc, 256>>>(px, pxb, pproj, l2g + (size_t)l*Hc, l2b + (size_t)l*Hc);
    }

    run_gemm_t<0,0>(pxb, pWcT, bc, plog, Mc, Vc, Hc);
    row_loss_kernel<<<Mc, 256>>>(labels);
    loss_reduce_kernel<<<1, 1024>>>((float*)d_out);
}

// round 6
// speedup vs baseline: 7.0822x; 1.2727x over previous
#include <cuda_runtime.h>
#include <cuda_bf16.h>
#include <math.h>
#include <stdint.h>

// Problem constants
#define Lc 12
#define Hc 768
#define NHc 12
#define DHc 64
#define FFc 3072
#define Vc 21128
#define Sc 512
#define Bc 8
#define Mc (Bc*Sc)          // 4096 tokens
#define SEPc 102
#define LN_EPS 1e-12f
#define QKVN 2304

typedef __nv_bfloat16 bf16;
typedef __nv_bfloat162 bf162;

// ---------------- Device scratch (static; no runtime allocation) ----------------
__device__ float g_x[Mc*Hc];               // fp32 residual stream
__device__ bf16  g_xb[Mc*Hc];              // bf16 copy of x (GEMM A operand)
__device__ bf16  g_qkvb[(size_t)Mc*QKVN];  // fused QKV output (bf16)
__device__ bf16  g_ctxb[Mc*Hc];            // attention output (bf16, feeds Wo)
__device__ float g_proj[Mc*Hc];
__device__ bf16  g_ffnb[(size_t)Mc*FFc];   // GELU output (bf16, feeds Wd)
__device__ float g_logits[(size_t)Mc*Vc];
__device__ float g_nll[Mc];
__device__ float g_valid[Mc];
__device__ int   g_sep[Bc];
__device__ float g_bqkv[Lc*QKVN];          // fused QKV bias
// Transposed (N-major, K-contiguous) bf16 weights
__device__ bf16 g_WqkvT[(size_t)Lc*QKVN*Hc];
__device__ bf16 g_WoT[Lc*Hc*Hc];
__device__ bf16 g_WiT[(size_t)Lc*FFc*Hc];
__device__ bf16 g_WdT[(size_t)Lc*Hc*FFc];
__device__ bf16 g_WcT[(size_t)Vc*Hc];

// ---------------- small PTX helpers (compute_103-safe) ----------------
__device__ __forceinline__ uint32_t smem_to_u32(const void* smem_ptr) {
    uint32_t addr;
    asm("{ .reg .u64 tmp; cvta.to.shared.u64 tmp, %1; cvt.u32.u64 %0, tmp; }"
        : "=r"(addr) : "l"(smem_ptr));
    return addr;
}
__device__ __forceinline__ void cp16(uint32_t dst, const void* src, bool pred) {
    uint32_t sz = pred ? 16u : 0u;
    asm volatile("cp.async.cg.shared.global [%0], [%1], 16, %2;"
                 :: "r"(dst), "l"(src), "r"(sz));
}
#define CP_COMMIT() asm volatile("cp.async.commit_group;" ::: "memory")
#define CP_WAIT0()  asm volatile("cp.async.wait_group 0;" ::: "memory")

__device__ __forceinline__ void mma_bf16(float* c, const uint32_t* a,
                                         uint32_t b0, uint32_t b1) {
    asm volatile(
        "mma.sync.aligned.m16n8k16.row.col.f32.bf16.bf16.f32 "
        "{%0,%1,%2,%3}, {%4,%5,%6,%7}, {%8,%9}, {%0,%1,%2,%3};"
        : "+f"(c[0]), "+f"(c[1]), "+f"(c[2]), "+f"(c[3])
        : "r"(a[0]), "r"(a[1]), "r"(a[2]), "r"(a[3]), "r"(b0), "r"(b1));
}

__device__ __forceinline__ float gelu_exact(float v) {
    return 0.5f * v * (1.0f + erff(v * 0.70710678118654752f));
}

// ---------------- Batched weight transpose + bf16 conversion ----------------
// out[n*K + k] = bf16(in[k*N + n]); blockIdx.z = layer
__global__ void transpose_bf16_b(const float* __restrict__ in, bf16* __restrict__ out,
                                 int K, int N, size_t inStride, size_t outStride)
{
    __shared__ float tile[32][33];
    in  += (size_t)blockIdx.z * inStride;
    out += (size_t)blockIdx.z * outStride;
    int kb = blockIdx.y * 32, nb = blockIdx.x * 32;
    int tx = threadIdx.x, ty = threadIdx.y;
    for (int i = ty; i < 32; i += 8) {
        int kk = kb + i, nn = nb + tx;
        tile[i][tx] = (kk < K && nn < N) ? in[(size_t)kk * N + nn] : 0.0f;
    }
    __syncthreads();
    for (int i = ty; i < 32; i += 8) {
        int nn = nb + i, kk = kb + tx;
        if (nn < N && kk < K) out[(size_t)nn * K + kk] = __float2bfloat16_rn(tile[tx][i]);
    }
}

// ---------------- fused QKV bias ----------------
__global__ void build_qkv_bias(const float* __restrict__ bq, const float* __restrict__ bk,
                               const float* __restrict__ bv)
{
    int i = blockIdx.x * 256 + threadIdx.x;
    if (i < Lc * QKVN) {
        int l = i / QKVN, c = i % QKVN;
        float v;
        if (c < Hc)            v = bq[l*Hc + c];
        else if (c < 2*Hc)     v = bk[l*Hc + c - Hc];
        else                   v = bv[l*Hc + c - 2*Hc];
        g_bqkv[i] = v;
    }
}

// ---------------- [SEP] position per batch row ----------------
__global__ void sep_kernel(const int* __restrict__ ids) {
    int b = threadIdx.x;
    if (b < Bc) {
        int s = Sc - 1;
        for (int i = 0; i < Sc; i++) {
            if (ids[b*Sc + i] == SEPc) { s = i; break; }
        }
        g_sep[b] = s;
    }
}

// ---------------- Embedding + LayerNorm (dual fp32 + bf16 output) ----------------
__global__ void embed_ln_kernel(const int* __restrict__ ids,
                                const float* __restrict__ we,
                                const float* __restrict__ pe,
                                const float* __restrict__ te,
                                const float* __restrict__ gg,
                                const float* __restrict__ bb)
{
    int row = blockIdx.x;
    int s   = row % Sc;
    int tid = threadIdx.x;
    __shared__ float buf[Hc];
    __shared__ float red[256];
    int id = ids[row];
    float lsum = 0.f;
    for (int j = tid; j < Hc; j += 256) {
        float val = we[(size_t)id*Hc + j] + pe[s*Hc + j] + te[j];
        buf[j] = val;
        lsum += val;
    }
    red[tid] = lsum; __syncthreads();
    for (int o = 128; o > 0; o >>= 1) { if (tid < o) red[tid] += red[tid+o]; __syncthreads(); }
    float mean = red[0] * (1.0f/Hc);
    __syncthreads();
    float lsq = 0.f;
    for (int j = tid; j < Hc; j += 256) { float d = buf[j]-mean; lsq += d*d; }
    red[tid] = lsq; __syncthreads();
    for (int o = 128; o > 0; o >>= 1) { if (tid < o) red[tid] += red[tid+o]; __syncthreads(); }
    float inv = rsqrtf(red[0]*(1.0f/Hc) + LN_EPS);
    for (int j = tid; j < Hc; j += 256) {
        float o = (buf[j]-mean)*inv*gg[j] + bb[j];
        g_x[(size_t)row*Hc + j]  = o;
        g_xb[(size_t)row*Hc + j] = __float2bfloat16_rn(o);
    }
}

// ---------------- Residual add + LayerNorm, dual output ----------------
__global__ void add_ln_kernel(float* __restrict__ x, bf16* __restrict__ xb,
                              const float* __restrict__ t,
                              const float* __restrict__ gg, const float* __restrict__ bb)
{
    int row = blockIdx.x;
    int tid = threadIdx.x;
    __shared__ float buf[Hc];
    __shared__ float red[256];
    float lsum = 0.f;
    for (int j = tid; j < Hc; j += 256) {
        float val = x[(size_t)row*Hc + j] + t[(size_t)row*Hc + j];
        buf[j] = val;
        lsum += val;
    }
    red[tid] = lsum; __syncthreads();
    for (int o = 128; o > 0; o >>= 1) { if (tid < o) red[tid] += red[tid+o]; __syncthreads(); }
    float mean = red[0] * (1.0f/Hc);
    __syncthreads();
    float lsq = 0.f;
    for (int j = tid; j < Hc; j += 256) { float d = buf[j]-mean; lsq += d*d; }
    red[tid] = lsq; __syncthreads();
    for (int o = 128; o > 0; o >>= 1) { if (tid < o) red[tid] += red[tid+o]; __syncthreads(); }
    float inv = rsqrtf(red[0]*(1.0f/Hc) + LN_EPS);
    for (int j = tid; j < Hc; j += 256) {
        float o = (buf[j]-mean)*inv*gg[j] + bb[j];
        x[(size_t)row*Hc + j]  = o;
        xb[(size_t)row*Hc + j] = __float2bfloat16_rn(o);
    }
}

// ======================= mma.sync bf16 GEMM =======================
#define STG_HW 5120            // halfwords per stage (128*40)
#define STG_B  10240           // bytes per stage
#define GEMM_SMEM_BYTES 40960  // 4 stages total (A0,A1,B0,B1)

template<int ACT, int OUTBF>
__global__ __launch_bounds__(256)
void tc_gemm(const bf16* __restrict__ A, const bf16* __restrict__ Bt,
             const float* __restrict__ bias, void* __restrict__ Cv,
             int M, int N, int K)
{
    extern __shared__ __align__(16) char smraw[];
    const uint32_t sbase = smem_to_u32(smraw);
    uint16_t* sH = (uint16_t*)smraw;

    const int t    = threadIdx.x;
    const int lane = t & 31;
    const int w    = t >> 5;
    const int wm   = w & 3;
    const int wn   = w >> 2;
    const int m0   = blockIdx.y * 128;
    const int n0   = blockIdx.x * 128;
    const int nk   = K >> 5;

    float acc[2][8][4];
#pragma unroll
    for (int mt = 0; mt < 2; mt++)
#pragma unroll
        for (int nt = 0; nt < 8; nt++)
#pragma unroll
            for (int i = 0; i < 4; i++) acc[mt][nt][i] = 0.f;

    auto load_stage = [&](int c) {
        const int s  = c & 1;
        const int k0 = c << 5;
        const uint32_t aB = sbase + (uint32_t)s * STG_B;
        const uint32_t bB = sbase + 2u * STG_B + (uint32_t)s * STG_B;
#pragma unroll
        for (int i = 0; i < 2; i++) {
            int idx = t + i * 256;
            int row = idx >> 2, q = idx & 3;
            cp16(aB + (uint32_t)(row * 80 + q * 16),
                 A + (size_t)(m0 + row) * K + k0 + q * 8, true);
            int nr = n0 + row;
            bool p = nr < N;
            int nrc = p ? nr : 0;
            cp16(bB + (uint32_t)(row * 80 + q * 16),
                 Bt + (size_t)nrc * K + k0 + q * 8, p);
        }
        CP_COMMIT();
    };

    const int lrow = lane >> 2;
    const int lk   = 2 * (lane & 3);

    load_stage(0);
    for (int c = 0; c < nk; c++) {
        CP_WAIT0();
        __syncthreads();
        if (c + 1 < nk) load_stage(c + 1);

        const int s = c & 1;
        const uint16_t* sAx = sH + s * STG_HW;
        const uint16_t* sBx = sH + 2 * STG_HW + s * STG_HW;
#pragma unroll
        for (int ks = 0; ks < 2; ks++) {
            const int kb = ks * 16;
            uint32_t af[2][4];
#pragma unroll
            for (int mt = 0; mt < 2; mt++) {
                const uint16_t* ap = sAx + (wm * 32 + mt * 16 + lrow) * 40 + kb + lk;
                af[mt][0] = *reinterpret_cast<const uint32_t*>(ap);
                af[mt][1] = *reinterpret_cast<const uint32_t*>(ap + 8 * 40);
                af[mt][2] = *reinterpret_cast<const uint32_t*>(ap + 8);
                af[mt][3] = *reinterpret_cast<const uint32_t*>(ap + 8 * 40 + 8);
            }
#pragma unroll
            for (int nt = 0; nt < 8; nt++) {
                const uint16_t* bp = sBx + (wn * 64 + nt * 8 + lrow) * 40 + kb + lk;
                uint32_t b0 = *reinterpret_cast<const uint32_t*>(bp);
                uint32_t b1 = *reinterpret_cast<const uint32_t*>(bp + 8);
                mma_bf16(acc[0][nt], af[0], b0, b1);
                mma_bf16(acc[1][nt], af[1], b0, b1);
            }
        }
        __syncthreads();
    }

    float* Cf = (float*)Cv;
    bf16*  Cb = (bf16*)Cv;
#pragma unroll
    for (int mt = 0; mt < 2; mt++) {
        int rlo = m0 + wm * 32 + mt * 16 + lrow;
        int rhi = rlo + 8;
#pragma unroll
        for (int nt = 0; nt < 8; nt++) {
            int col = n0 + wn * 64 + nt * 8 + lk;
            if (col < N) {
                float b0v = bias[col], b1v = bias[col + 1];
                float v0 = acc[mt][nt][0] + b0v;
                float v1 = acc[mt][nt][1] + b1v;
                float v2 = acc[mt][nt][2] + b0v;
                float v3 = acc[mt][nt][3] + b1v;
                if (ACT == 1) {
                    v0 = gelu_exact(v0); v1 = gelu_exact(v1);
                    v2 = gelu_exact(v2); v3 = gelu_exact(v3);
                }
                if (OUTBF) {
                    bf162 lo; lo.x = __float2bfloat16_rn(v0); lo.y = __float2bfloat16_rn(v1);
                    bf162 hi; hi.x = __float2bfloat16_rn(v2); hi.y = __float2bfloat16_rn(v3);
                    *reinterpret_cast<bf162*>(Cb + (size_t)rlo * N + col) = lo;
                    *reinterpret_cast<bf162*>(Cb + (size_t)rhi * N + col) = hi;
                } else {
                    float2 lo; lo.x = v0; lo.y = v1;
                    float2 hi; hi.x = v2; hi.y = v3;
                    *reinterpret_cast<float2*>(Cf + (size_t)rlo * N + col) = lo;
                    *reinterpret_cast<float2*>(Cf + (size_t)rhi * N + col) = hi;
                }
            }
        }
    }
}

// ======================= Tensor-core attention =======================
// Block = (b, h, 32-q tile), 256 threads (8 warps).
// SMEM layout:
//   sQ  [32][40]  bf16 @ 0       (2560 B)
//   sK  [128][40] bf16 @ 2560    (10240 B)  } union with
//   sVT [64][136] bf16 @ 2560    (17408 B)  }
//   sS  [32][516] f32  @ 19968   (66048 B)
//   sP  [32][520] bf16 @ 86016   (33280 B)
//   sInv[32]      f32  @ 119296
#define AT_SQ    0
#define AT_SKV   2560
#define AT_SS    19968
#define AT_SP    86016
#define AT_SINV  119296
#define AT_SMEM  119424

__global__ __launch_bounds__(256, 1)
void attn3_kernel(const bf16* __restrict__ qkv, bf16* __restrict__ ctx)
{
    extern __shared__ __align__(16) char sm[];
    uint16_t* sQ  = (uint16_t*)(sm + AT_SQ);
    uint16_t* sK  = (uint16_t*)(sm + AT_SKV);
    uint16_t* sVT = (uint16_t*)(sm + AT_SKV);
    float*    sS  = (float*)   (sm + AT_SS);
    uint16_t* sP  = (uint16_t*)(sm + AT_SP);
    float*    sInv= (float*)   (sm + AT_SINV);

    const int t = threadIdx.x, lane = t & 31, w = t >> 5;
    const int q0 = blockIdx.x * 32;
    const int h  = blockIdx.y;
    const int b  = blockIdx.z;
    const int sp = g_sep[b];
    const int lrow = lane >> 2;
    const int lk   = 2 * (lane & 3);

    const bf16* qbase = qkv + (size_t)(b * Sc + q0) * QKVN + h * DHc;
    const bf16* kbase = qkv + (size_t)(b * Sc) * QKVN + Hc + h * DHc;
    const bf16* vbase = qkv + (size_t)(b * Sc) * QKVN + 2 * Hc + h * DHc;

    // ---- load Q tile (32 x 64): 512 chunks of 4 halfwords ----
#pragma unroll
    for (int i = 0; i < 2; i++) {
        int idx = t + i * 256;
        int r = idx >> 4, cg = idx & 15;
        uint2 v = *reinterpret_cast<const uint2*>(qbase + (size_t)r * QKVN + cg * 4);
        *reinterpret_cast<uint2*>(sQ + r * 40 + cg * 4) = v;
    }
    __syncthreads();

    // ---- QK^T scores ----
    for (int c = 0; c < 4; c++) {
        const int kb0 = c * 128;
        // K tile 128 x 64: 2048 chunks of 4 halfwords (i < 8 !)
#pragma unroll
        for (int i = 0; i < 8; i++) {
            int idx = t + i * 256;
            int r = idx >> 4, cg = idx & 15;
            uint2 v = *reinterpret_cast<const uint2*>(kbase + (size_t)(kb0 + r) * QKVN + cg * 4);
            *reinterpret_cast<uint2*>(sK + r * 40 + cg * 4) = v;
        }
        __syncthreads();

        float sacc[2][2][4];
#pragma unroll
        for (int mt = 0; mt < 2; mt++)
#pragma unroll
            for (int nt = 0; nt < 2; nt++)
#pragma unroll
                for (int i = 0; i < 4; i++) sacc[mt][nt][i] = 0.f;

#pragma unroll
        for (int ks = 0; ks < 4; ks++) {          // d chunks of 16
            const int kb = ks * 16;
            uint32_t af[2][4];
#pragma unroll
            for (int mt = 0; mt < 2; mt++) {
                const uint16_t* ap = sQ + (mt * 16 + lrow) * 40 + kb + lk;
                af[mt][0] = *reinterpret_cast<const uint32_t*>(ap);
                af[mt][1] = *reinterpret_cast<const uint32_t*>(ap + 8 * 40);
                af[mt][2] = *reinterpret_cast<const uint32_t*>(ap + 8);
                af[mt][3] = *reinterpret_cast<const uint32_t*>(ap + 8 * 40 + 8);
            }
#pragma unroll
            for (int nt = 0; nt < 2; nt++) {
                const uint16_t* bp = sK + (w * 16 + nt * 8 + lrow) * 40 + kb + lk;
                uint32_t b0 = *reinterpret_cast<const uint32_t*>(bp);
                uint32_t b1 = *reinterpret_cast<const uint32_t*>(bp + 8);
                mma_bf16(sacc[0][nt], af[0], b0, b1);
                mma_bf16(sacc[1][nt], af[1], b0, b1);
            }
        }
        // write scaled+masked scores
#pragma unroll
        for (int mt = 0; mt < 2; mt++) {
            const int r  = mt * 16 + lrow;
            const int qg0 = q0 + r;
            const int qg1 = qg0 + 8;
#pragma unroll
            for (int nt = 0; nt < 2; nt++) {
                const int kcol = kb0 + w * 16 + nt * 8 + lk;
                float s0 = sacc[mt][nt][0] * 0.125f;
                float s1 = sacc[mt][nt][1] * 0.125f;
                float s2 = sacc[mt][nt][2] * 0.125f;
                float s3 = sacc[mt][nt][3] * 0.125f;
                bool pfx0 = (qg0 <= sp), pfx1 = (qg1 <= sp);
                bool ka = (kcol <= sp), kb1 = (kcol + 1 <= sp);
                if (!((kcol     <= qg0) || (pfx0 && ka)))  s0 -= 1e4f;
                if (!((kcol + 1 <= qg0) || (pfx0 && kb1))) s1 -= 1e4f;
                if (!((kcol     <= qg1) || (pfx1 && ka)))  s2 -= 1e4f;
                if (!((kcol + 1 <= qg1) || (pfx1 && kb1))) s3 -= 1e4f;
                float2 lo; lo.x = s0; lo.y = s1;
                float2 hi; hi.x = s2; hi.y = s3;
                *reinterpret_cast<float2*>(sS + r * 516 + kcol) = lo;
                *reinterpret_cast<float2*>(sS + (r + 8) * 516 + kcol) = hi;
            }
        }
        __syncthreads();
    }

    // ---- softmax (8 threads per row); write unnormalized exp as bf16 P ----
    {
        const int r = t >> 3, sub = t & 7;
        float m = -3.4e38f;
        for (int j = sub; j < Sc; j += 8) m = fmaxf(m, sS[r * 516 + j]);
#pragma unroll
        for (int msk = 1; msk < 8; msk <<= 1)
            m = fmaxf(m, __shfl_xor_sync(0xffffffffu, m, msk));
        float sum = 0.f;
        for (int j = sub; j < Sc; j += 8) {
            float e = expf(sS[r * 516 + j] - m);
            sP[r * 520 + j] = __bfloat16_as_ushort(__float2bfloat16_rn(e));
            sum += e;
        }
#pragma unroll
        for (int msk = 1; msk < 8; msk <<= 1)
            sum += __shfl_xor_sync(0xffffffffu, sum, msk);
        if (sub == 0) sInv[r] = 1.0f / sum;
    }
    __syncthreads();

    // ---- ctx = P @ V (warp w owns d columns w*8..w*8+7) ----
    float cacc[2][4];
#pragma unroll
    for (int mt = 0; mt < 2; mt++)
#pragma unroll
        for (int i = 0; i < 4; i++) cacc[mt][i] = 0.f;

    for (int c = 0; c < 4; c++) {
        const int kb0 = c * 128;
        // load V chunk transposed: sVT[d][kpos]; 2048 chunks
#pragma unroll
        for (int i = 0; i < 8; i++) {
            int idx = t + i * 256;
            int kpos = idx >> 4, dg = idx & 15;
            uint2 v = *reinterpret_cast<const uint2*>(vbase + (size_t)(kb0 + kpos) * QKVN + dg * 4);
            sVT[(dg * 4 + 0) * 136 + kpos] = (uint16_t)(v.x);
            sVT[(dg * 4 + 1) * 136 + kpos] = (uint16_t)(v.x >> 16);
            sVT[(dg * 4 + 2) * 136 + kpos] = (uint16_t)(v.y);
            sVT[(dg * 4 + 3) * 136 + kpos] = (uint16_t)(v.y >> 16);
        }
        __syncthreads();
#pragma unroll
        for (int ks = 0; ks < 8; ks++) {
            const int kb = ks * 16;
            uint32_t af[2][4];
#pragma unroll
            for (int mt = 0; mt < 2; mt++) {
                const uint16_t* ap = sP + (mt * 16 + lrow) * 520 + kb0 + kb + lk;
                af[mt][0] = *reinterpret_cast<const uint32_t*>(ap);
                af[mt][1] = *reinterpret_cast<const uint32_t*>(ap + 8 * 520);
                af[mt][2] = *reinterpret_cast<const uint32_t*>(ap + 8);
                af[mt][3] = *reinterpret_cast<const uint32_t*>(ap + 8 * 520 + 8);
            }
            const uint16_t* bp = sVT + (w * 8 + lrow) * 136 + kb + lk;
            uint32_t b0 = *reinterpret_cast<const uint32_t*>(bp);
            uint32_t b1 = *reinterpret_cast<const uint32_t*>(bp + 8);
            mma_bf16(cacc[0], af[0], b0, b1);
            mma_bf16(cacc[1], af[1], b0, b1);
        }
        __syncthreads();
    }
    // epilogue: normalize and store bf16 ctx
#pragma unroll
    for (int mt = 0; mt < 2; mt++) {
        const int r = mt * 16 + lrow;
        const float inv0 = sInv[r], inv1 = sInv[r + 8];
        const int d0 = w * 8 + lk;
        bf162 lo, hi;
        lo.x = __float2bfloat16_rn(cacc[mt][0] * inv0);
        lo.y = __float2bfloat16_rn(cacc[mt][1] * inv0);
        hi.x = __float2bfloat16_rn(cacc[mt][2] * inv1);
        hi.y = __float2bfloat16_rn(cacc[mt][3] * inv1);
        *reinterpret_cast<bf162*>(ctx + (size_t)(b * Sc + q0 + r)     * Hc + h * DHc + d0) = lo;
        *reinterpret_cast<bf162*>(ctx + (size_t)(b * Sc + q0 + r + 8) * Hc + h * DHc + d0) = hi;
    }
}

// ---------------- Per-row log-softmax NLL ----------------
__global__ void row_loss_kernel(const int* __restrict__ labels)
{
    int row = blockIdx.x;
    int tid = threadIdx.x;
    const float* lr = g_logits + (size_t)row * Vc;
    __shared__ float red[256];

    float m = -3.4e38f;
    for (int j = tid; j < Vc; j += 256) m = fmaxf(m, lr[j]);
    red[tid] = m; __syncthreads();
    for (int o = 128; o > 0; o >>= 1) { if (tid < o) red[tid] = fmaxf(red[tid], red[tid+o]); __syncthreads(); }
    m = red[0];
    __syncthreads();

    float s = 0.f;
    for (int j = tid; j < Vc; j += 256) s += expf(lr[j] - m);
    red[tid] = s; __syncthreads();
    for (int o = 128; o > 0; o >>= 1) { if (tid < o) red[tid] += red[tid+o]; __syncthreads(); }

    if (tid == 0) {
        int lab = labels[row];
        if (lab >= 0) {
            g_nll[row]   = (m + logf(red[0])) - lr[lab];
            g_valid[row] = 1.0f;
        } else {
            g_nll[row]   = 0.0f;
            g_valid[row] = 0.0f;
        }
    }
}

// ---------------- Deterministic final reduction ----------------
__global__ void loss_reduce_kernel(float* __restrict__ out)
{
    __shared__ float rs[1024];
    __shared__ float rc[1024];
    int tid = threadIdx.x;
    float s = 0.f, c = 0.f;
    for (int i = tid; i < Mc; i += 1024) { s += g_nll[i]; c += g_valid[i]; }
    rs[tid] = s; rc[tid] = c; __syncthreads();
    for (int o = 512; o > 0; o >>= 1) {
        if (tid < o) { rs[tid] += rs[tid+o]; rc[tid] += rc[tid+o]; }
        __syncthreads();
    }
    if (tid == 0) out[0] = rs[0] / fmaxf(rc[0], 1.0f);
}

// ---------------- Host orchestration ----------------
static void run_tr_b(const float* in, bf16* out, int K, int N,
                     size_t inStride, size_t outStride, int layers)
{
    dim3 g((N + 31) / 32, (K + 31) / 32, layers);
    transpose_bf16_b<<<g, dim3(32, 8)>>>(in, out, K, N, inStride, outStride);
}

template<int ACT, int OUTBF>
static void run_gemm_t(const bf16* A, const bf16* Bt, const float* bias, void* C,
                       int M, int N, int K)
{
    dim3 grid((N + 127) / 128, M / 128);
    tc_gemm<ACT, OUTBF><<<grid, 256, GEMM_SMEM_BYTES>>>(A, Bt, bias, C, M, N, K);
}

extern "C" void kernel_launch(void* const* d_in, const int* in_sizes, int n_in,
                              void* d_out, int out_size)
{
    (void)in_sizes; (void)n_in; (void)out_size;

    const int*   ids      = (const int*)  d_in[0];
    const int*   labels   = (const int*)  d_in[1];
    const float* word_emb = (const float*)d_in[2];
    const float* pos_emb  = (const float*)d_in[3];
    const float* type_emb = (const float*)d_in[4];
    const float* eg       = (const float*)d_in[5];
    const float* eb       = (const float*)d_in[6];
    const float* Wq       = (const float*)d_in[7];
    const float* bq       = (const float*)d_in[8];
    const float* Wk       = (const float*)d_in[9];
    const float* bk       = (const float*)d_in[10];
    const float* Wv       = (const float*)d_in[11];
    const float* bv       = (const float*)d_in[12];
    const float* Wo       = (const float*)d_in[13];
    const float* bo       = (const float*)d_in[14];
    const float* l1g      = (const float*)d_in[15];
    const float* l1b      = (const float*)d_in[16];
    const float* Wi       = (const float*)d_in[17];
    const float* bi       = (const float*)d_in[18];
    const float* Wd       = (const float*)d_in[19];
    const float* bd       = (const float*)d_in[20];
    const float* l2g      = (const float*)d_in[21];
    const float* l2b      = (const float*)d_in[22];
    const float* Wc       = (const float*)d_in[23];
    const float* bc       = (const float*)d_in[24];

    cudaFuncSetAttribute(attn3_kernel, cudaFuncAttributeMaxDynamicSharedMemorySize, AT_SMEM);

    void* p;
    cudaGetSymbolAddress(&p, g_x);      float* px    = (float*)p;
    cudaGetSymbolAddress(&p, g_xb);     bf16*  pxb   = (bf16*)p;
    cudaGetSymbolAddress(&p, g_qkvb);   bf16*  pqkvb = (bf16*)p;
    cudaGetSymbolAddress(&p, g_ctxb);   bf16*  pctxb = (bf16*)p;
    cudaGetSymbolAddress(&p, g_proj);   float* pproj = (float*)p;
    cudaGetSymbolAddress(&p, g_ffnb);   bf16*  pffnb = (bf16*)p;
    cudaGetSymbolAddress(&p, g_logits); float* plog  = (float*)p;
    cudaGetSymbolAddress(&p, g_bqkv);   float* pbqkv = (float*)p;
    cudaGetSymbolAddress(&p, g_WqkvT);  bf16*  pWqkvT= (bf16*)p;
    cudaGetSymbolAddress(&p, g_WoT);    bf16*  pWoT  = (bf16*)p;
    cudaGetSymbolAddress(&p, g_WiT);    bf16*  pWiT  = (bf16*)p;
    cudaGetSymbolAddress(&p, g_WdT);    bf16*  pWdT  = (bf16*)p;
    cudaGetSymbolAddress(&p, g_WcT);    bf16*  pWcT  = (bf16*)p;

    // Batched weight transposes (7 launches)
    const size_t HH = (size_t)Hc * Hc;
    run_tr_b(Wq, pWqkvT,                    Hc, Hc, HH, (size_t)QKVN*Hc, Lc);
    run_tr_b(Wk, pWqkvT + HH,               Hc, Hc, HH, (size_t)QKVN*Hc, Lc);
    run_tr_b(Wv, pWqkvT + 2*HH,             Hc, Hc, HH, (size_t)QKVN*Hc, Lc);
    run_tr_b(Wo, pWoT,                      Hc, Hc, HH, HH, Lc);
    run_tr_b(Wi, pWiT,  Hc, FFc, (size_t)Hc*FFc, (size_t)FFc*Hc, Lc);
    run_tr_b(Wd, pWdT,  FFc, Hc, (size_t)FFc*Hc, (size_t)Hc*FFc, Lc);
    run_tr_b(Wc, pWcT,  Hc, Vc,  0, 0, 1);

    build_qkv_bias<<<(Lc*QKVN + 255)/256, 256>>>(bq, bk, bv);
    sep_kernel<<<1, 32>>>(ids);
    embed_ln_kernel<<<Mc, 256>>>(ids, word_emb, pos_emb, type_emb, eg, eb);

    for (int l = 0; l < Lc; l++) {
        run_gemm_t<0,1>(pxb, pWqkvT + (size_t)l*QKVN*Hc, pbqkv + (size_t)l*QKVN,
                        pqkvb, Mc, QKVN, Hc);
        attn3_kernel<<<dim3(Sc/32, NHc, Bc), 256, AT_SMEM>>>(pqkvb, pctxb);
        run_gemm_t<0,0>(pctxb, pWoT + (size_t)l*HH, bo + (size_t)l*Hc, pproj, Mc, Hc, Hc);
        add_ln_kernel<<<Mc, 256>>>(px, pxb, pproj, l1g + (size_t)l*Hc, l1b + (size_t)l*Hc);
        run_gemm_t<1,1>(pxb,   pWiT + (size_t)l*FFc*Hc, bi + (size_t)l*FFc, pffnb, Mc, FFc, Hc);
        run_gemm_t<0,0>(pffnb, pWdT + (size_t)l*Hc*FFc, bd + (size_t)l*Hc, pproj, Mc, Hc, FFc);
        add_ln_kernel<<<Mc, 256>>>(px, pxb, pproj, l2g + (size_t)l*Hc, l2b + (size_t)l*Hc);
    }

    run_gemm_t<0,0>(pxb, pWcT, bc, plog, Mc, Vc, Hc);
    row_loss_kernel<<<Mc, 256>>>(labels);
    loss_reduce_kernel<<<1, 1024>>>((float*)d_out);
}

// round 7
// speedup vs baseline: 8.0458x; 1.1361x over previous
#include <cuda_runtime.h>
#include <cuda_bf16.h>
#include <math.h>
#include <stdint.h>

// Problem constants
#define Lc 12
#define Hc 768
#define NHc 12
#define DHc 64
#define FFc 3072
#define Vc 21128
#define Sc 512
#define Bc 8
#define Mc (Bc*Sc)          // 4096 tokens
#define SEPc 102
#define LN_EPS 1e-12f
#define QKVN 2304
#define NTILES 166          // ceil(Vc/128)

typedef __nv_bfloat16 bf16;
typedef __nv_bfloat162 bf162;

// ---------------- Device scratch (static; no runtime allocation) ----------------
__device__ float g_x[Mc*Hc];               // fp32 residual stream
__device__ bf16  g_xb[Mc*Hc];              // bf16 copy of x (GEMM A operand)
__device__ bf16  g_qkvb[(size_t)Mc*QKVN];  // fused QKV output (bf16)
__device__ bf16  g_ctxb[Mc*Hc];            // attention output (bf16, feeds Wo)
__device__ float g_proj[Mc*Hc];
__device__ bf16  g_ffnb[(size_t)Mc*FFc];   // GELU output (bf16, feeds Wd)
__device__ float g_pmax[(size_t)Mc*NTILES];
__device__ float g_psum[(size_t)Mc*NTILES];
__device__ float g_labv[Mc];
__device__ float g_nll[Mc];
__device__ float g_valid[Mc];
__device__ int   g_sep[Bc];
__device__ float g_bqkv[Lc*QKVN];          // fused QKV bias
// Transposed (N-major, K-contiguous) bf16 weights
__device__ bf16 g_WqkvT[(size_t)Lc*QKVN*Hc];
__device__ bf16 g_WoT[Lc*Hc*Hc];
__device__ bf16 g_WiT[(size_t)Lc*FFc*Hc];
__device__ bf16 g_WdT[(size_t)Lc*Hc*FFc];
__device__ bf16 g_WcT[(size_t)Vc*Hc];

// ---------------- small PTX helpers (compute_103-safe) ----------------
__device__ __forceinline__ uint32_t smem_to_u32(const void* smem_ptr) {
    uint32_t addr;
    asm("{ .reg .u64 tmp; cvta.to.shared.u64 tmp, %1; cvt.u32.u64 %0, tmp; }"
        : "=r"(addr) : "l"(smem_ptr));
    return addr;
}
__device__ __forceinline__ void cp16(uint32_t dst, const void* src, bool pred) {
    uint32_t sz = pred ? 16u : 0u;
    asm volatile("cp.async.cg.shared.global [%0], [%1], 16, %2;"
                 :: "r"(dst), "l"(src), "r"(sz));
}
#define CP_COMMIT() asm volatile("cp.async.commit_group;" ::: "memory")
#define CP_WAIT0()  asm volatile("cp.async.wait_group 0;" ::: "memory")

__device__ __forceinline__ void mma_bf16(float* c, const uint32_t* a,
                                         uint32_t b0, uint32_t b1) {
    asm volatile(
        "mma.sync.aligned.m16n8k16.row.col.f32.bf16.bf16.f32 "
        "{%0,%1,%2,%3}, {%4,%5,%6,%7}, {%8,%9}, {%0,%1,%2,%3};"
        : "+f"(c[0]), "+f"(c[1]), "+f"(c[2]), "+f"(c[3])
        : "r"(a[0]), "r"(a[1]), "r"(a[2]), "r"(a[3]), "r"(b0), "r"(b1));
}

__device__ __forceinline__ float gelu_exact(float v) {
    return 0.5f * v * (1.0f + erff(v * 0.70710678118654752f));
}

// ---------------- Batched weight transpose + bf16 conversion ----------------
__global__ void transpose_bf16_b(const float* __restrict__ in, bf16* __restrict__ out,
                                 int K, int N, size_t inStride, size_t outStride)
{
    __shared__ float tile[32][33];
    in  += (size_t)blockIdx.z * inStride;
    out += (size_t)blockIdx.z * outStride;
    int kb = blockIdx.y * 32, nb = blockIdx.x * 32;
    int tx = threadIdx.x, ty = threadIdx.y;
    for (int i = ty; i < 32; i += 8) {
        int kk = kb + i, nn = nb + tx;
        tile[i][tx] = (kk < K && nn < N) ? in[(size_t)kk * N + nn] : 0.0f;
    }
    __syncthreads();
    for (int i = ty; i < 32; i += 8) {
        int nn = nb + i, kk = kb + tx;
        if (nn < N && kk < K) out[(size_t)nn * K + kk] = __float2bfloat16_rn(tile[tx][i]);
    }
}

// ---------------- fused QKV bias ----------------
__global__ void build_qkv_bias(const float* __restrict__ bq, const float* __restrict__ bk,
                               const float* __restrict__ bv)
{
    int i = blockIdx.x * 256 + threadIdx.x;
    if (i < Lc * QKVN) {
        int l = i / QKVN, c = i % QKVN;
        float v;
        if (c < Hc)            v = bq[l*Hc + c];
        else if (c < 2*Hc)     v = bk[l*Hc + c - Hc];
        else                   v = bv[l*Hc + c - 2*Hc];
        g_bqkv[i] = v;
    }
}

// ---------------- [SEP] position per batch row ----------------
__global__ void sep_kernel(const int* __restrict__ ids) {
    int b = threadIdx.x;
    if (b < Bc) {
        int s = Sc - 1;
        for (int i = 0; i < Sc; i++) {
            if (ids[b*Sc + i] == SEPc) { s = i; break; }
        }
        g_sep[b] = s;
    }
}

// ---------------- Embedding + LayerNorm (dual fp32 + bf16 output) ----------------
__global__ void embed_ln_kernel(const int* __restrict__ ids,
                                const float* __restrict__ we,
                                const float* __restrict__ pe,
                                const float* __restrict__ te,
                                const float* __restrict__ gg,
                                const float* __restrict__ bb)
{
    int row = blockIdx.x;
    int s   = row % Sc;
    int tid = threadIdx.x;
    __shared__ float buf[Hc];
    __shared__ float wsum[8], wsq[8];
    int id = ids[row];
    float lsum = 0.f, lsq = 0.f;
    for (int j = tid; j < Hc; j += 256) {
        float val = we[(size_t)id*Hc + j] + pe[s*Hc + j] + te[j];
        buf[j] = val;
        lsum += val; lsq += val * val;
    }
#pragma unroll
    for (int o = 16; o > 0; o >>= 1) {
        lsum += __shfl_xor_sync(0xffffffffu, lsum, o);
        lsq  += __shfl_xor_sync(0xffffffffu, lsq,  o);
    }
    if ((tid & 31) == 0) { wsum[tid >> 5] = lsum; wsq[tid >> 5] = lsq; }
    __syncthreads();
    float ts = 0.f, tq = 0.f;
#pragma unroll
    for (int i = 0; i < 8; i++) { ts += wsum[i]; tq += wsq[i]; }
    float mean = ts * (1.0f/Hc);
    float var  = fmaxf(tq * (1.0f/Hc) - mean * mean, 0.f);
    float inv  = rsqrtf(var + LN_EPS);
    for (int j = tid; j < Hc; j += 256) {
        float o = (buf[j]-mean)*inv*gg[j] + bb[j];
        g_x[(size_t)row*Hc + j]  = o;
        g_xb[(size_t)row*Hc + j] = __float2bfloat16_rn(o);
    }
}

// ---------------- Residual add + LayerNorm, dual output ----------------
__global__ void add_ln_kernel(float* __restrict__ x, bf16* __restrict__ xb,
                              const float* __restrict__ t,
                              const float* __restrict__ gg, const float* __restrict__ bb)
{
    int row = blockIdx.x;
    int tid = threadIdx.x;
    __shared__ float buf[Hc];
    __shared__ float wsum[8], wsq[8];
    float lsum = 0.f, lsq = 0.f;
    for (int j = tid; j < Hc; j += 256) {
        float val = x[(size_t)row*Hc + j] + t[(size_t)row*Hc + j];
        buf[j] = val;
        lsum += val; lsq += val * val;
    }
#pragma unroll
    for (int o = 16; o > 0; o >>= 1) {
        lsum += __shfl_xor_sync(0xffffffffu, lsum, o);
        lsq  += __shfl_xor_sync(0xffffffffu, lsq,  o);
    }
    if ((tid & 31) == 0) { wsum[tid >> 5] = lsum; wsq[tid >> 5] = lsq; }
    __syncthreads();
    float ts = 0.f, tq = 0.f;
#pragma unroll
    for (int i = 0; i < 8; i++) { ts += wsum[i]; tq += wsq[i]; }
    float mean = ts * (1.0f/Hc);
    float var  = fmaxf(tq * (1.0f/Hc) - mean * mean, 0.f);
    float inv  = rsqrtf(var + LN_EPS);
    for (int j = tid; j < Hc; j += 256) {
        float o = (buf[j]-mean)*inv*gg[j] + bb[j];
        x[(size_t)row*Hc + j]  = o;
        xb[(size_t)row*Hc + j] = __float2bfloat16_rn(o);
    }
}

// ======================= mma.sync bf16 GEMM =======================
#define STG_HW 5120            // halfwords per stage (128*40)
#define STG_B  10240           // bytes per stage
#define GEMM_SMEM_BYTES 40960  // 4 stages total (A0,A1,B0,B1)

template<int ACT, int OUTBF>
__global__ __launch_bounds__(256)
void tc_gemm(const bf16* __restrict__ A, const bf16* __restrict__ Bt,
             const float* __restrict__ bias, void* __restrict__ Cv,
             int M, int N, int K)
{
    extern __shared__ __align__(16) char smraw[];
    const uint32_t sbase = smem_to_u32(smraw);
    uint16_t* sH = (uint16_t*)smraw;

    const int t    = threadIdx.x;
    const int lane = t & 31;
    const int w    = t >> 5;
    const int wm   = w & 3;
    const int wn   = w >> 2;
    const int m0   = blockIdx.y * 128;
    const int n0   = blockIdx.x * 128;
    const int nk   = K >> 5;

    float acc[2][8][4];
#pragma unroll
    for (int mt = 0; mt < 2; mt++)
#pragma unroll
        for (int nt = 0; nt < 8; nt++)
#pragma unroll
            for (int i = 0; i < 4; i++) acc[mt][nt][i] = 0.f;

    auto load_stage = [&](int c) {
        const int s  = c & 1;
        const int k0 = c << 5;
        const uint32_t aB = sbase + (uint32_t)s * STG_B;
        const uint32_t bB = sbase + 2u * STG_B + (uint32_t)s * STG_B;
#pragma unroll
        for (int i = 0; i < 2; i++) {
            int idx = t + i * 256;
            int row = idx >> 2, q = idx & 3;
            cp16(aB + (uint32_t)(row * 80 + q * 16),
                 A + (size_t)(m0 + row) * K + k0 + q * 8, true);
            int nr = n0 + row;
            bool p = nr < N;
            int nrc = p ? nr : 0;
            cp16(bB + (uint32_t)(row * 80 + q * 16),
                 Bt + (size_t)nrc * K + k0 + q * 8, p);
        }
        CP_COMMIT();
    };

    const int lrow = lane >> 2;
    const int lk   = 2 * (lane & 3);

    load_stage(0);
    for (int c = 0; c < nk; c++) {
        CP_WAIT0();
        __syncthreads();
        if (c + 1 < nk) load_stage(c + 1);

        const int s = c & 1;
        const uint16_t* sAx = sH + s * STG_HW;
        const uint16_t* sBx = sH + 2 * STG_HW + s * STG_HW;
#pragma unroll
        for (int ks = 0; ks < 2; ks++) {
            const int kb = ks * 16;
            uint32_t af[2][4];
#pragma unroll
            for (int mt = 0; mt < 2; mt++) {
                const uint16_t* ap = sAx + (wm * 32 + mt * 16 + lrow) * 40 + kb + lk;
                af[mt][0] = *reinterpret_cast<const uint32_t*>(ap);
                af[mt][1] = *reinterpret_cast<const uint32_t*>(ap + 8 * 40);
                af[mt][2] = *reinterpret_cast<const uint32_t*>(ap + 8);
                af[mt][3] = *reinterpret_cast<const uint32_t*>(ap + 8 * 40 + 8);
            }
#pragma unroll
            for (int nt = 0; nt < 8; nt++) {
                const uint16_t* bp = sBx + (wn * 64 + nt * 8 + lrow) * 40 + kb + lk;
                uint32_t b0 = *reinterpret_cast<const uint32_t*>(bp);
                uint32_t b1 = *reinterpret_cast<const uint32_t*>(bp + 8);
                mma_bf16(acc[0][nt], af[0], b0, b1);
                mma_bf16(acc[1][nt], af[1], b0, b1);
            }
        }
        __syncthreads();
    }

    float* Cf = (float*)Cv;
    bf16*  Cb = (bf16*)Cv;
#pragma unroll
    for (int mt = 0; mt < 2; mt++) {
        int rlo = m0 + wm * 32 + mt * 16 + lrow;
        int rhi = rlo + 8;
#pragma unroll
        for (int nt = 0; nt < 8; nt++) {
            int col = n0 + wn * 64 + nt * 8 + lk;
            if (col < N) {
                float b0v = bias[col], b1v = bias[col + 1];
                float v0 = acc[mt][nt][0] + b0v;
                float v1 = acc[mt][nt][1] + b1v;
                float v2 = acc[mt][nt][2] + b0v;
                float v3 = acc[mt][nt][3] + b1v;
                if (ACT == 1) {
                    v0 = gelu_exact(v0); v1 = gelu_exact(v1);
                    v2 = gelu_exact(v2); v3 = gelu_exact(v3);
                }
                if (OUTBF) {
                    bf162 lo; lo.x = __float2bfloat16_rn(v0); lo.y = __float2bfloat16_rn(v1);
                    bf162 hi; hi.x = __float2bfloat16_rn(v2); hi.y = __float2bfloat16_rn(v3);
                    *reinterpret_cast<bf162*>(Cb + (size_t)rlo * N + col) = lo;
                    *reinterpret_cast<bf162*>(Cb + (size_t)rhi * N + col) = hi;
                } else {
                    float2 lo; lo.x = v0; lo.y = v1;
                    float2 hi; hi.x = v2; hi.y = v3;
                    *reinterpret_cast<float2*>(Cf + (size_t)rlo * N + col) = lo;
                    *reinterpret_cast<float2*>(Cf + (size_t)rhi * N + col) = hi;
                }
            }
        }
    }
}

// ======================= Classifier GEMM + fused log-softmax partials =======================
// Same mainloop as tc_gemm; epilogue computes per-(row, n-tile) max and sum-exp
// partials (online-softmax mergeable) and captures the label logit.
__global__ __launch_bounds__(256)
void tc_gemm_loss(const bf16* __restrict__ A, const bf16* __restrict__ Bt,
                  const float* __restrict__ bias, const int* __restrict__ labels,
                  int M, int N, int K)
{
    extern __shared__ __align__(16) char smraw[];
    const uint32_t sbase = smem_to_u32(smraw);
    uint16_t* sH = (uint16_t*)smraw;
    __shared__ float sMx[128][2];
    __shared__ float sSm[128][2];

    const int t    = threadIdx.x;
    const int lane = t & 31;
    const int w    = t >> 5;
    const int wm   = w & 3;
    const int wn   = w >> 2;
    const int mBase = blockIdx.y * 128;
    const int nBase = blockIdx.x * 128;
    const int nk   = K >> 5;

    float acc[2][8][4];
#pragma unroll
    for (int mt = 0; mt < 2; mt++)
#pragma unroll
        for (int nt = 0; nt < 8; nt++)
#pragma unroll
            for (int i = 0; i < 4; i++) acc[mt][nt][i] = 0.f;

    auto load_stage = [&](int c) {
        const int s  = c & 1;
        const int k0 = c << 5;
        const uint32_t aB = sbase + (uint32_t)s * STG_B;
        const uint32_t bB = sbase + 2u * STG_B + (uint32_t)s * STG_B;
#pragma unroll
        for (int i = 0; i < 2; i++) {
            int idx = t + i * 256;
            int row = idx >> 2, q = idx & 3;
            cp16(aB + (uint32_t)(row * 80 + q * 16),
                 A + (size_t)(mBase + row) * K + k0 + q * 8, true);
            int nr = nBase + row;
            bool p = nr < N;
            int nrc = p ? nr : 0;
            cp16(bB + (uint32_t)(row * 80 + q * 16),
                 Bt + (size_t)nrc * K + k0 + q * 8, p);
        }
        CP_COMMIT();
    };

    const int lrow = lane >> 2;
    const int lk   = 2 * (lane & 3);

    load_stage(0);
    for (int c = 0; c < nk; c++) {
        CP_WAIT0();
        __syncthreads();
        if (c + 1 < nk) load_stage(c + 1);

        const int s = c & 1;
        const uint16_t* sAx = sH + s * STG_HW;
        const uint16_t* sBx = sH + 2 * STG_HW + s * STG_HW;
#pragma unroll
        for (int ks = 0; ks < 2; ks++) {
            const int kb = ks * 16;
            uint32_t af[2][4];
#pragma unroll
            for (int mt = 0; mt < 2; mt++) {
                const uint16_t* ap = sAx + (wm * 32 + mt * 16 + lrow) * 40 + kb + lk;
                af[mt][0] = *reinterpret_cast<const uint32_t*>(ap);
                af[mt][1] = *reinterpret_cast<const uint32_t*>(ap + 8 * 40);
                af[mt][2] = *reinterpret_cast<const uint32_t*>(ap + 8);
                af[mt][3] = *reinterpret_cast<const uint32_t*>(ap + 8 * 40 + 8);
            }
#pragma unroll
            for (int nt = 0; nt < 8; nt++) {
                const uint16_t* bp = sBx + (wn * 64 + nt * 8 + lrow) * 40 + kb + lk;
                uint32_t b0 = *reinterpret_cast<const uint32_t*>(bp);
                uint32_t b1 = *reinterpret_cast<const uint32_t*>(bp + 8);
                mma_bf16(acc[0][nt], af[0], b0, b1);
                mma_bf16(acc[1][nt], af[1], b0, b1);
            }
        }
        __syncthreads();
    }

    // ---- loss epilogue ----
    float vmax[2][2];
#pragma unroll
    for (int mt = 0; mt < 2; mt++) { vmax[mt][0] = -3.4e38f; vmax[mt][1] = -3.4e38f; }
#pragma unroll
    for (int mt = 0; mt < 2; mt++)
#pragma unroll
        for (int nt = 0; nt < 8; nt++) {
            int col = nBase + wn * 64 + nt * 8 + lk;
            float b0v = (col     < N) ? bias[col]     : 0.f;
            float b1v = (col + 1 < N) ? bias[col + 1] : 0.f;
            float v0 = (col     < N) ? acc[mt][nt][0] + b0v : -3.4e38f;
            float v1 = (col + 1 < N) ? acc[mt][nt][1] + b1v : -3.4e38f;
            float v2 = (col     < N) ? acc[mt][nt][2] + b0v : -3.4e38f;
            float v3 = (col + 1 < N) ? acc[mt][nt][3] + b1v : -3.4e38f;
            acc[mt][nt][0] = v0; acc[mt][nt][1] = v1;
            acc[mt][nt][2] = v2; acc[mt][nt][3] = v3;
            vmax[mt][0] = fmaxf(vmax[mt][0], fmaxf(v0, v1));
            vmax[mt][1] = fmaxf(vmax[mt][1], fmaxf(v2, v3));
        }
#pragma unroll
    for (int mt = 0; mt < 2; mt++)
#pragma unroll
        for (int hh = 0; hh < 2; hh++) {
            vmax[mt][hh] = fmaxf(vmax[mt][hh], __shfl_xor_sync(0xffffffffu, vmax[mt][hh], 1));
            vmax[mt][hh] = fmaxf(vmax[mt][hh], __shfl_xor_sync(0xffffffffu, vmax[mt][hh], 2));
        }
#pragma unroll
    for (int mt = 0; mt < 2; mt++) {
        int rin = wm * 32 + mt * 16 + lrow;
        sMx[rin][wn]     = vmax[mt][0];
        sMx[rin + 8][wn] = vmax[mt][1];
    }
    __syncthreads();
    float rmax[2][2], rsum[2][2];
#pragma unroll
    for (int mt = 0; mt < 2; mt++) {
        int rin = wm * 32 + mt * 16 + lrow;
        rmax[mt][0] = fmaxf(sMx[rin][0],     sMx[rin][1]);
        rmax[mt][1] = fmaxf(sMx[rin + 8][0], sMx[rin + 8][1]);
        rsum[mt][0] = 0.f; rsum[mt][1] = 0.f;
    }
#pragma unroll
    for (int mt = 0; mt < 2; mt++)
#pragma unroll
        for (int nt = 0; nt < 8; nt++) {
            rsum[mt][0] += __expf(acc[mt][nt][0] - rmax[mt][0])
                         + __expf(acc[mt][nt][1] - rmax[mt][0]);
            rsum[mt][1] += __expf(acc[mt][nt][2] - rmax[mt][1])
                         + __expf(acc[mt][nt][3] - rmax[mt][1]);
        }
#pragma unroll
    for (int mt = 0; mt < 2; mt++)
#pragma unroll
        for (int hh = 0; hh < 2; hh++) {
            rsum[mt][hh] += __shfl_xor_sync(0xffffffffu, rsum[mt][hh], 1);
            rsum[mt][hh] += __shfl_xor_sync(0xffffffffu, rsum[mt][hh], 2);
        }
#pragma unroll
    for (int mt = 0; mt < 2; mt++) {
        int rin = wm * 32 + mt * 16 + lrow;
        sSm[rin][wn]     = rsum[mt][0];
        sSm[rin + 8][wn] = rsum[mt][1];
    }
    __syncthreads();
    if (wn == 0 && (lane & 3) == 0) {
#pragma unroll
        for (int mt = 0; mt < 2; mt++) {
            int rin = wm * 32 + mt * 16 + lrow;
            int gr0 = mBase + rin, gr1 = gr0 + 8;
            g_pmax[(size_t)gr0 * NTILES + blockIdx.x] = rmax[mt][0];
            g_psum[(size_t)gr0 * NTILES + blockIdx.x] = sSm[rin][0] + sSm[rin][1];
            g_pmax[(size_t)gr1 * NTILES + blockIdx.x] = rmax[mt][1];
            g_psum[(size_t)gr1 * NTILES + blockIdx.x] = sSm[rin + 8][0] + sSm[rin + 8][1];
        }
    }
    // label logit capture (unique writer: the thread owning that column)
#pragma unroll
    for (int mt = 0; mt < 2; mt++) {
        int rin = wm * 32 + mt * 16 + lrow;
        int gr0 = mBase + rin, gr1 = gr0 + 8;
        int lab0 = labels[gr0], lab1 = labels[gr1];
#pragma unroll
        for (int nt = 0; nt < 8; nt++) {
            int col = nBase + wn * 64 + nt * 8 + lk;
            if (col == lab0)     g_labv[gr0] = acc[mt][nt][0];
            if (col + 1 == lab0) g_labv[gr0] = acc[mt][nt][1];
            if (col == lab1)     g_labv[gr1] = acc[mt][nt][2];
            if (col + 1 == lab1) g_labv[gr1] = acc[mt][nt][3];
        }
    }
}

// ---------------- merge loss partials: one warp per row ----------------
__global__ void loss_merge(const int* __restrict__ labels)
{
    int row  = (blockIdx.x * blockDim.x + threadIdx.x) >> 5;
    int lane = threadIdx.x & 31;
    if (row >= Mc) return;
    const float* pm = g_pmax + (size_t)row * NTILES;
    const float* ps = g_psum + (size_t)row * NTILES;
    float M = -3.4e38f;
    for (int i = lane; i < NTILES; i += 32) M = fmaxf(M, pm[i]);
#pragma unroll
    for (int o = 16; o > 0; o >>= 1) M = fmaxf(M, __shfl_xor_sync(0xffffffffu, M, o));
    float S = 0.f;
    for (int i = lane; i < NTILES; i += 32) S += ps[i] * __expf(pm[i] - M);
#pragma unroll
    for (int o = 16; o > 0; o >>= 1) S += __shfl_xor_sync(0xffffffffu, S, o);
    if (lane == 0) {
        int lab = labels[row];
        if (lab >= 0) {
            g_nll[row]   = (M + __logf(S)) - g_labv[row];
            g_valid[row] = 1.0f;
        } else {
            g_nll[row]   = 0.0f;
            g_valid[row] = 0.0f;
        }
    }
}

// ======================= Tensor-core attention =======================
// Mask = (k <= max(q, sep)) exactly, so: no bias needed, softmax exp only over
// allowed range, and whole 128-k chunks beyond max(q0+31, sep) are skipped.
#define AT_SQ    0
#define AT_SKV   2560
#define AT_SS    19968
#define AT_SP    86016
#define AT_SINV  119296
#define AT_SMEM  119424

__global__ __launch_bounds__(256, 1)
void attn3_kernel(const bf16* __restrict__ qkv, bf16* __restrict__ ctx)
{
    extern __shared__ __align__(16) char sm[];
    uint16_t* sQ  = (uint16_t*)(sm + AT_SQ);
    uint16_t* sK  = (uint16_t*)(sm + AT_SKV);
    uint16_t* sVT = (uint16_t*)(sm + AT_SKV);
    float*    sS  = (float*)   (sm + AT_SS);
    uint16_t* sP  = (uint16_t*)(sm + AT_SP);
    float*    sInv= (float*)   (sm + AT_SINV);

    const int t = threadIdx.x, lane = t & 31, w = t >> 5;
    const int q0 = blockIdx.x * 32;
    const int h  = blockIdx.y;
    const int b  = blockIdx.z;
    const int sp = g_sep[b];
    const int lrow = lane >> 2;
    const int lk   = 2 * (lane & 3);
    const int Lmax = max(q0 + 31, sp);
    const int nch  = (Lmax >> 7) + 1;       // 128-k chunks actually needed

    const bf16* qbase = qkv + (size_t)(b * Sc + q0) * QKVN + h * DHc;
    const bf16* kbase = qkv + (size_t)(b * Sc) * QKVN + Hc + h * DHc;
    const bf16* vbase = qkv + (size_t)(b * Sc) * QKVN + 2 * Hc + h * DHc;

    // ---- load Q tile (32 x 64) ----
#pragma unroll
    for (int i = 0; i < 2; i++) {
        int idx = t + i * 256;
        int r = idx >> 4, cg = idx & 15;
        uint2 v = *reinterpret_cast<const uint2*>(qbase + (size_t)r * QKVN + cg * 4);
        *reinterpret_cast<uint2*>(sQ + r * 40 + cg * 4) = v;
    }
    __syncthreads();

    // ---- QK^T scores (only needed chunks) ----
    for (int c = 0; c < nch; c++) {
        const int kb0 = c * 128;
#pragma unroll
        for (int i = 0; i < 8; i++) {
            int idx = t + i * 256;
            int r = idx >> 4, cg = idx & 15;
            uint2 v = *reinterpret_cast<const uint2*>(kbase + (size_t)(kb0 + r) * QKVN + cg * 4);
            *reinterpret_cast<uint2*>(sK + r * 40 + cg * 4) = v;
        }
        __syncthreads();

        float sacc[2][2][4];
#pragma unroll
        for (int mt = 0; mt < 2; mt++)
#pragma unroll
            for (int nt = 0; nt < 2; nt++)
#pragma unroll
                for (int i = 0; i < 4; i++) sacc[mt][nt][i] = 0.f;

#pragma unroll
        for (int ks = 0; ks < 4; ks++) {
            const int kb = ks * 16;
            uint32_t af[2][4];
#pragma unroll
            for (int mt = 0; mt < 2; mt++) {
                const uint16_t* ap = sQ + (mt * 16 + lrow) * 40 + kb + lk;
                af[mt][0] = *reinterpret_cast<const uint32_t*>(ap);
                af[mt][1] = *reinterpret_cast<const uint32_t*>(ap + 8 * 40);
                af[mt][2] = *reinterpret_cast<const uint32_t*>(ap + 8);
                af[mt][3] = *reinterpret_cast<const uint32_t*>(ap + 8 * 40 + 8);
            }
#pragma unroll
            for (int nt = 0; nt < 2; nt++) {
                const uint16_t* bp = sK + (w * 16 + nt * 8 + lrow) * 40 + kb + lk;
                uint32_t b0 = *reinterpret_cast<const uint32_t*>(bp);
                uint32_t b1 = *reinterpret_cast<const uint32_t*>(bp + 8);
                mma_bf16(sacc[0][nt], af[0], b0, b1);
                mma_bf16(sacc[1][nt], af[1], b0, b1);
            }
        }
        // write scaled scores (no mask bias needed; masked entries never read)
#pragma unroll
        for (int mt = 0; mt < 2; mt++) {
            const int r = mt * 16 + lrow;
#pragma unroll
            for (int nt = 0; nt < 2; nt++) {
                const int kcol = kb0 + w * 16 + nt * 8 + lk;
                float2 lo; lo.x = sacc[mt][nt][0] * 0.125f; lo.y = sacc[mt][nt][1] * 0.125f;
                float2 hi; hi.x = sacc[mt][nt][2] * 0.125f; hi.y = sacc[mt][nt][3] * 0.125f;
                *reinterpret_cast<float2*>(sS + r * 516 + kcol) = lo;
                *reinterpret_cast<float2*>(sS + (r + 8) * 516 + kcol) = hi;
            }
        }
        __syncthreads();
    }

    // ---- softmax (8 threads / row) over allowed k only; zero-fill the rest ----
    {
        const int r = t >> 3, sub = t & 7;
        const int Lk = max(q0 + r, sp);     // inclusive allowed limit for this row
        const int jmax = nch * 128;
        float m = -3.4e38f;
        for (int j = sub; j <= Lk; j += 8) m = fmaxf(m, sS[r * 516 + j]);
#pragma unroll
        for (int msk = 1; msk < 8; msk <<= 1)
            m = fmaxf(m, __shfl_xor_sync(0xffffffffu, m, msk));
        float sum = 0.f;
        for (int j = sub; j < jmax; j += 8) {
            if (j <= Lk) {
                float e = __expf(sS[r * 516 + j] - m);
                sP[r * 520 + j] = __bfloat16_as_ushort(__float2bfloat16_rn(e));
                sum += e;
            } else {
                sP[r * 520 + j] = 0;
            }
        }
#pragma unroll
        for (int msk = 1; msk < 8; msk <<= 1)
            sum += __shfl_xor_sync(0xffffffffu, sum, msk);
        if (sub == 0) sInv[r] = 1.0f / sum;
    }
    __syncthreads();

    // ---- ctx = P @ V (warp w owns d columns w*8..w*8+7); skip empty chunks ----
    float cacc[2][4];
#pragma unroll
    for (int mt = 0; mt < 2; mt++)
#pragma unroll
        for (int i = 0; i < 4; i++) cacc[mt][i] = 0.f;

    for (int c = 0; c < nch; c++) {
        const int kb0 = c * 128;
#pragma unroll
        for (int i = 0; i < 8; i++) {
            int idx = t + i * 256;
            int kpos = idx >> 4, dg = idx & 15;
            uint2 v = *reinterpret_cast<const uint2*>(vbase + (size_t)(kb0 + kpos) * QKVN + dg * 4);
            sVT[(dg * 4 + 0) * 136 + kpos] = (uint16_t)(v.x);
            sVT[(dg * 4 + 1) * 136 + kpos] = (uint16_t)(v.x >> 16);
            sVT[(dg * 4 + 2) * 136 + kpos] = (uint16_t)(v.y);
            sVT[(dg * 4 + 3) * 136 + kpos] = (uint16_t)(v.y >> 16);
        }
        __syncthreads();
#pragma unroll
        for (int ks = 0; ks < 8; ks++) {
            const int kb = ks * 16;
            uint32_t af[2][4];
#pragma unroll
            for (int mt = 0; mt < 2; mt++) {
                const uint16_t* ap = sP + (mt * 16 + lrow) * 520 + kb0 + kb + lk;
                af[mt][0] = *reinterpret_cast<const uint32_t*>(ap);
                af[mt][1] = *reinterpret_cast<const uint32_t*>(ap + 8 * 520);
                af[mt][2] = *reinterpret_cast<const uint32_t*>(ap + 8);
                af[mt][3] = *reinterpret_cast<const uint32_t*>(ap + 8 * 520 + 8);
            }
            const uint16_t* bp = sVT + (w * 8 + lrow) * 136 + kb + lk;
            uint32_t b0 = *reinterpret_cast<const uint32_t*>(bp);
            uint32_t b1 = *reinterpret_cast<const uint32_t*>(bp + 8);
            mma_bf16(cacc[0], af[0], b0, b1);
            mma_bf16(cacc[1], af[1], b0, b1);
        }
        __syncthreads();
    }
#pragma unroll
    for (int mt = 0; mt < 2; mt++) {
        const int r = mt * 16 + lrow;
        const float inv0 = sInv[r], inv1 = sInv[r + 8];
        const int d0 = w * 8 + lk;
        bf162 lo, hi;
        lo.x = __float2bfloat16_rn(cacc[mt][0] * inv0);
        lo.y = __float2bfloat16_rn(cacc[mt][1] * inv0);
        hi.x = __float2bfloat16_rn(cacc[mt][2] * inv1);
        hi.y = __float2bfloat16_rn(cacc[mt][3] * inv1);
        *reinterpret_cast<bf162*>(ctx + (size_t)(b * Sc + q0 + r)     * Hc + h * DHc + d0) = lo;
        *reinterpret_cast<bf162*>(ctx + (size_t)(b * Sc + q0 + r + 8) * Hc + h * DHc + d0) = hi;
    }
}

// ---------------- Deterministic final reduction ----------------
__global__ void loss_reduce_kernel(float* __restrict__ out)
{
    __shared__ float rs[1024];
    __shared__ float rc[1024];
    int tid = threadIdx.x;
    float s = 0.f, c = 0.f;
    for (int i = tid; i < Mc; i += 1024) { s += g_nll[i]; c += g_valid[i]; }
    rs[tid] = s; rc[tid] = c; __syncthreads();
    for (int o = 512; o > 0; o >>= 1) {
        if (tid < o) { rs[tid] += rs[tid+o]; rc[tid] += rc[tid+o]; }
        __syncthreads();
    }
    if (tid == 0) out[0] = rs[0] / fmaxf(rc[0], 1.0f);
}

// ---------------- Host orchestration ----------------
static void run_tr_b(const float* in, bf16* out, int K, int N,
                     size_t inStride, size_t outStride, int layers)
{
    dim3 g((N + 31) / 32, (K + 31) / 32, layers);
    transpose_bf16_b<<<g, dim3(32, 8)>>>(in, out, K, N, inStride, outStride);
}

template<int ACT, int OUTBF>
static void run_gemm_t(const bf16* A, const bf16* Bt, const float* bias, void* C,
                       int M, int N, int K)
{
    dim3 grid((N + 127) / 128, M / 128);
    tc_gemm<ACT, OUTBF><<<grid, 256, GEMM_SMEM_BYTES>>>(A, Bt, bias, C, M, N, K);
}

extern "C" void kernel_launch(void* const* d_in, const int* in_sizes, int n_in,
                              void* d_out, int out_size)
{
    (void)in_sizes; (void)n_in; (void)out_size;

    const int*   ids      = (const int*)  d_in[0];
    const int*   labels   = (const int*)  d_in[1];
    const float* word_emb = (const float*)d_in[2];
    const float* pos_emb  = (const float*)d_in[3];
    const float* type_emb = (const float*)d_in[4];
    const float* eg       = (const float*)d_in[5];
    const float* eb       = (const float*)d_in[6];
    const float* Wq       = (const float*)d_in[7];
    const float* bq       = (const float*)d_in[8];
    const float* Wk       = (const float*)d_in[9];
    const float* bk       = (const float*)d_in[10];
    const float* Wv       = (const float*)d_in[11];
    const float* bv       = (const float*)d_in[12];
    const float* Wo       = (const float*)d_in[13];
    const float* bo       = (const float*)d_in[14];
    const float* l1g      = (const float*)d_in[15];
    const float* l1b      = (const float*)d_in[16];
    const float* Wi       = (const float*)d_in[17];
    const float* bi       = (const float*)d_in[18];
    const float* Wd       = (const float*)d_in[19];
    const float* bd       = (const float*)d_in[20];
    const float* l2g      = (const float*)d_in[21];
    const float* l2b      = (const float*)d_in[22];
    const float* Wc       = (const float*)d_in[23];
    const float* bc       = (const float*)d_in[24];

    cudaFuncSetAttribute(attn3_kernel, cudaFuncAttributeMaxDynamicSharedMemorySize, AT_SMEM);

    void* p;
    cudaGetSymbolAddress(&p, g_x);      float* px    = (float*)p;
    cudaGetSymbolAddress(&p, g_xb);     bf16*  pxb   = (bf16*)p;
    cudaGetSymbolAddress(&p, g_qkvb);   bf16*  pqkvb = (bf16*)p;
    cudaGetSymbolAddress(&p, g_ctxb);   bf16*  pctxb = (bf16*)p;
    cudaGetSymbolAddress(&p, g_proj);   float* pproj = (float*)p;
    cudaGetSymbolAddress(&p, g_ffnb);   bf16*  pffnb = (bf16*)p;
    cudaGetSymbolAddress(&p, g_bqkv);   float* pbqkv = (float*)p;
    cudaGetSymbolAddress(&p, g_WqkvT);  bf16*  pWqkvT= (bf16*)p;
    cudaGetSymbolAddress(&p, g_WoT);    bf16*  pWoT  = (bf16*)p;
    cudaGetSymbolAddress(&p, g_WiT);    bf16*  pWiT  = (bf16*)p;
    cudaGetSymbolAddress(&p, g_WdT);    bf16*  pWdT  = (bf16*)p;
    cudaGetSymbolAddress(&p, g_WcT);    bf16*  pWcT  = (bf16*)p;

    // Batched weight transposes (7 launches)
    const size_t HH = (size_t)Hc * Hc;
    run_tr_b(Wq, pWqkvT,                    Hc, Hc, HH, (size_t)QKVN*Hc, Lc);
    run_tr_b(Wk, pWqkvT + HH,               Hc, Hc, HH, (size_t)QKVN*Hc, Lc);
    run_tr_b(Wv, pWqkvT + 2*HH,             Hc, Hc, HH, (size_t)QKVN*Hc, Lc);
    run_tr_b(Wo, pWoT,                      Hc, Hc, HH, HH, Lc);
    run_tr_b(Wi, pWiT,  Hc, FFc, (size_t)Hc*FFc, (size_t)FFc*Hc, Lc);
    run_tr_b(Wd, pWdT,  FFc, Hc, (size_t)FFc*Hc, (size_t)Hc*FFc, Lc);
    run_tr_b(Wc, pWcT,  Hc, Vc,  0, 0, 1);

    build_qkv_bias<<<(Lc*QKVN + 255)/256, 256>>>(bq, bk, bv);
    sep_kernel<<<1, 32>>>(ids);
    embed_ln_kernel<<<Mc, 256>>>(ids, word_emb, pos_emb, type_emb, eg, eb);

    for (int l = 0; l < Lc; l++) {
        run_gemm_t<0,1>(pxb, pWqkvT + (size_t)l*QKVN*Hc, pbqkv + (size_t)l*QKVN,
                        pqkvb, Mc, QKVN, Hc);
        attn3_kernel<<<dim3(Sc/32, NHc, Bc), 256, AT_SMEM>>>(pqkvb, pctxb);
        run_gemm_t<0,0>(pctxb, pWoT + (size_t)l*HH, bo + (size_t)l*Hc, pproj, Mc, Hc, Hc);
        add_ln_kernel<<<Mc, 256>>>(px, pxb, pproj, l1g + (size_t)l*Hc, l1b + (size_t)l*Hc);
        run_gemm_t<1,1>(pxb,   pWiT + (size_t)l*FFc*Hc, bi + (size_t)l*FFc, pffnb, Mc, FFc, Hc);
        run_gemm_t<0,0>(pffnb, pWdT + (size_t)l*Hc*FFc, bd + (size_t)l*Hc, pproj, Mc, Hc, FFc);
        add_ln_kernel<<<Mc, 256>>>(px, pxb, pproj, l2g + (size_t)l*Hc, l2b + (size_t)l*Hc);
    }

    // classifier + fused loss
    {
        dim3 grid(NTILES, Mc / 128);
        tc_gemm_loss<<<grid, 256, GEMM_SMEM_BYTES>>>(pxb, pWcT, bc, labels, Mc, Vc, Hc);
    }
    loss_merge<<<(Mc * 32 + 255) / 256, 256>>>(labels);
    loss_reduce_kernel<<<1, 1024>>>((float*)d_out);
}